// round 13
// baseline (speedup 1.0000x reference)
#include <cuda_runtime.h>
#include <cuda_fp16.h>
#include <stdint.h>

#define Bb 4
#define Tt 512
#define Hh 16
#define Gg 4
#define HD 128
#define CACHEN 3584
#define SS 4096

// Scratch (static device arrays; no allocation allowed)
__device__ __half g_xh   [2048*2048];    // fp16 x               [M,K] K-major
__device__ __half g_wqkvh[3072*2048];    // fp16 qkv weights     [N,K] K-major
__device__ __half g_owh  [2048*2048];    // fp16 o_w             [N,K] K-major
__device__ float  g_qkv  [2048*3072];    // fused projection output (fp32)
__device__ __half g_qh   [Bb*Hh*Tt*HD];  // fp16 Q (pre-scaled) [B,H,T,HD]
__device__ __half g_ctxh [Bb*Tt*Hh*HD];  // fp16 ctx [B,T,H*HD]
__device__ __half g_kh   [Bb*Gg*SS*HD];  // fp16 k_full [B,G,S,HD]
__device__ __half g_vh   [Bb*Gg*HD*SS];  // fp16 v_full transposed [B,G,HD,S], keys permuted in 16-groups
__device__ unsigned long long g_mb[Bb*Tt*64]; // mask bitmask: [b*T + t][tile]

// Side-stream resources, created once at program load (before any capture).
struct GpuRes {
    cudaStream_t s2;
    cudaEvent_t e0, e2;
    GpuRes() {
        cudaStreamCreateWithFlags(&s2, cudaStreamNonBlocking);
        cudaEventCreateWithFlags(&e0, cudaEventDisableTiming);
        cudaEventCreateWithFlags(&e2, cudaEventDisableTiming);
    }
};
static GpuRes g_res;

// pack two floats into half2 (lo, hi)
__device__ __forceinline__ unsigned ph2(float lo, float hi) {
    unsigned r;
    asm("cvt.rn.f16x2.f32 %0, %1, %2;" : "=r"(r) : "f"(hi), "f"(lo));
    return r;
}

__device__ __forceinline__ void mma16(float* c,
    unsigned a0, unsigned a1, unsigned a2, unsigned a3,
    unsigned b0, unsigned b1)
{
    asm volatile(
        "mma.sync.aligned.m16n8k16.row.col.f32.f16.f16.f32 "
        "{%0,%1,%2,%3}, {%4,%5,%6,%7}, {%8,%9}, {%0,%1,%2,%3};"
        : "+f"(c[0]), "+f"(c[1]), "+f"(c[2]), "+f"(c[3])
        : "r"(a0), "r"(a1), "r"(a2), "r"(a3), "r"(b0), "r"(b1));
}

#define CPASYNC16(dst_sm, src_gm) \
    asm volatile("cp.async.cg.shared.global [%0], [%1], 16;\n" \
                 :: "r"(dst_sm), "l"(src_gm))

// key permutation within a 16-group so PV B-fragments are contiguous uint2
__device__ __forceinline__ int perm16(int s) {
    return ((s >> 1) & 3) * 4 + ((s >> 3) & 1) * 2 + (s & 1);
}

// ---------------------------------------------------------------------------
// Prep kernels
// ---------------------------------------------------------------------------
__global__ __launch_bounds__(256) void conv_x_kernel(
    const float4* __restrict__ src, uint2* __restrict__ dst, int n4)
{
    int i = blockIdx.x * blockDim.x + threadIdx.x;
    if (i >= n4) return;
    float4 v = src[i];
    dst[i] = make_uint2(ph2(v.x, v.y), ph2(v.z, v.w));
}

// Pack mask bytes into per-tile u64 bitmasks: out[row][tile], row = b*T+t.
__global__ __launch_bounds__(256) void pack_mask_kernel(
    const uint8_t* __restrict__ mask, unsigned long long* __restrict__ out)
{
    int i = blockIdx.x * blockDim.x + threadIdx.x;
    if (i >= Bb * Tt * 64) return;
    int tile = i & 63, row = i >> 6;
    const unsigned long long* src = (const unsigned long long*)
        (mask + (size_t)row * SS + tile * 64);
    unsigned long long bits = 0;
    #pragma unroll
    for (int c = 0; c < 8; c++) {
        unsigned long long w = src[c];
        #pragma unroll
        for (int j = 0; j < 8; j++)
            if ((w >> (8 * j)) & 0xFFull)
                bits |= 1ull << (c * 8 + j);
    }
    out[i] = bits;
}

// Transposed qkv weight pack (vectorized): dst[n][k] = fp16(w[k][n]).
__global__ __launch_bounds__(256) void pack_wqkvT_kernel(
    const float* __restrict__ qw, const float* __restrict__ kw,
    const float* __restrict__ vw, __half* __restrict__ dst)
{
    __shared__ float tile[64][65];
    int k0 = blockIdx.x << 6;
    int n0 = blockIdx.y << 6;
    const float* src; int ncol, nbase;
    if (n0 < 2048)      { src = qw; ncol = 2048; nbase = 0; }
    else if (n0 < 2560) { src = kw; ncol = 512;  nbase = 2048; }
    else                { src = vw; ncol = 512;  nbase = 2560; }

    #pragma unroll
    for (int t = 0; t < 4; t++) {
        int idx = threadIdx.x + (t << 8);
        int r = idx >> 4, c4 = (idx & 15) << 2;
        float4 v = *(const float4*)&src[(size_t)(k0 + r) * ncol + (n0 - nbase) + c4];
        tile[r][c4] = v.x; tile[r][c4 + 1] = v.y;
        tile[r][c4 + 2] = v.z; tile[r][c4 + 3] = v.w;
    }
    __syncthreads();
    #pragma unroll
    for (int t = 0; t < 2; t++) {
        int idx = threadIdx.x + (t << 8);
        int n = idx >> 3, c8 = idx & 7;
        __half h[8];
        #pragma unroll
        for (int j = 0; j < 8; j++)
            h[j] = __float2half_rn(tile[c8 * 8 + j][n]);
        *(uint4*)&dst[(size_t)(n0 + n) * 2048 + k0 + c8 * 8] = *(uint4*)h;
    }
}

// o_w transpose: dst[n][k] = fp16(src[k][n]), 2048x2048 (side stream, hidden)
__global__ __launch_bounds__(256) void transpose_ow_kernel(
    const float* __restrict__ src, __half* __restrict__ dst)
{
    __shared__ float tile[32][33];
    int k0 = blockIdx.x << 5, n0 = blockIdx.y << 5;
    int tx = threadIdx.x & 31, ty = threadIdx.x >> 5;
    #pragma unroll
    for (int r = 0; r < 32; r += 8)
        tile[ty + r][tx] = src[(size_t)(k0 + ty + r) * 2048 + n0 + tx];
    __syncthreads();
    #pragma unroll
    for (int r = 0; r < 32; r += 8)
        dst[(size_t)(n0 + ty + r) * 2048 + k0 + tx] =
            __float2half_rn(tile[tx][ty + r]);
}

// V: transpose + fp16 + key permutation into [bg][d][s'], sources direct.
__global__ __launch_bounds__(256) void transpose_v_kernel(
    const float* __restrict__ cache_v, const float* __restrict__ qkv,
    __half* __restrict__ dst)
{
    __shared__ float tile[32][33];
    int bg = blockIdx.z;
    int b = bg >> 2, g = bg & 3;
    int s0 = blockIdx.x << 5, d0 = blockIdx.y << 5;
    int tx = threadIdx.x & 31, ty = threadIdx.x >> 5;

    if (s0 < CACHEN) {
        const float* s = cache_v + (size_t)bg * CACHEN * HD;
        #pragma unroll
        for (int r = 0; r < 32; r += 8)
            tile[ty + r][tx] = s[(size_t)(s0 + ty + r) * HD + d0 + tx];
    } else {
        #pragma unroll
        for (int r = 0; r < 32; r += 8) {
            int t = s0 + ty + r - CACHEN;
            tile[ty + r][tx] =
                qkv[(size_t)(b * Tt + t) * 3072 + 2560 + g * HD + d0 + tx];
        }
    }
    __syncthreads();
    __half* d = dst + (size_t)bg * HD * SS;
    int sp = s0 + (tx & ~15) + perm16(tx & 15);
    #pragma unroll
    for (int r = 0; r < 32; r += 8)
        d[(size_t)(d0 + ty + r) * SS + sp] = __float2half_rn(tile[tx][ty + r]);
}

// ---------------------------------------------------------------------------
// fp16 GEMM (unchanged).
// ---------------------------------------------------------------------------
__global__ __launch_bounds__(256, 2) void gemm_h(
    const __half* __restrict__ A, const __half* __restrict__ Bm,
    float* __restrict__ C, int M, int N, int K)
{
    extern __shared__ unsigned sm[];
    unsigned* As = sm;
    unsigned* Bs = sm + 2 * 128 * 40;
    const int STG = 128 * 40;

    int tid = threadIdx.x, lane = tid & 31, warp = tid >> 5;
    int g = lane >> 2, tg = lane & 3;
    int m0 = blockIdx.y << 7, n0 = blockIdx.x << 7;
    int wm = (warp >> 2) << 6, wn = (warp & 3) << 5;

    float acc[4][4][4];
    #pragma unroll
    for (int i = 0; i < 4; i++)
        #pragma unroll
        for (int j = 0; j < 4; j++)
            #pragma unroll
            for (int e = 0; e < 4; e++) acc[i][j][e] = 0.0f;

    auto load_stage = [&](int it) {
        int s = it & 1;
        int k0 = it << 6;
        #pragma unroll
        for (int t = 0; t < 4; t++) {
            int c = tid + (t << 8);
            int row = c >> 3, ch = c & 7;
            unsigned da = (unsigned)__cvta_generic_to_shared(
                &As[s * STG + row * 40 + ch * 4]);
            CPASYNC16(da, A + (size_t)(m0 + row) * K + k0 + ch * 8);
            unsigned db = (unsigned)__cvta_generic_to_shared(
                &Bs[s * STG + row * 40 + ch * 4]);
            CPASYNC16(db, Bm + (size_t)(n0 + row) * K + k0 + ch * 8);
        }
        asm volatile("cp.async.commit_group;\n");
    };

    int niter = K >> 6;
    load_stage(0);

    for (int it = 0; it < niter; it++) {
        if (it + 1 < niter) {
            load_stage(it + 1);
            asm volatile("cp.async.wait_group 1;\n");
        } else {
            asm volatile("cp.async.wait_group 0;\n");
        }
        __syncthreads();

        const unsigned* Ab = As + (it & 1) * STG;
        const unsigned* Bbuf = Bs + (it & 1) * STG;
        #pragma unroll
        for (int ks = 0; ks < 4; ks++) {
            uint2 alo[4], ahi[4];
            #pragma unroll
            for (int mt = 0; mt < 4; mt++) {
                int r = wm + mt * 16;
                alo[mt] = *(const uint2*)&Ab[(r + g) * 40 + ks * 8 + 2 * tg];
                ahi[mt] = *(const uint2*)&Ab[(r + g + 8) * 40 + ks * 8 + 2 * tg];
            }
            #pragma unroll
            for (int nt = 0; nt < 4; nt++) {
                uint2 bb = *(const uint2*)&Bbuf[(wn + nt * 8 + g) * 40 + ks * 8 + 2 * tg];
                #pragma unroll
                for (int mt = 0; mt < 4; mt++)
                    mma16(acc[mt][nt], alo[mt].x, ahi[mt].x, alo[mt].y, ahi[mt].y,
                          bb.x, bb.y);
            }
        }
        __syncthreads();
    }

    #pragma unroll
    for (int mt = 0; mt < 4; mt++)
        #pragma unroll
        for (int nt = 0; nt < 4; nt++) {
            int r0 = m0 + wm + mt * 16 + g;
            int c  = n0 + wn + nt * 8 + 2 * tg;
            float2 v0 = make_float2(acc[mt][nt][0], acc[mt][nt][1]);
            float2 v1 = make_float2(acc[mt][nt][2], acc[mt][nt][3]);
            *(float2*)&C[(size_t)r0 * N + c] = v0;
            *(float2*)&C[(size_t)(r0 + 8) * N + c] = v1;
        }
}

// ---------------------------------------------------------------------------
// Fused per-head RMSNorm + RoPE; fp32 out (nullable) + fp16 out (nullable).
// ---------------------------------------------------------------------------
__global__ __launch_bounds__(128) void norm_rope_kernel(
    const float* __restrict__ raw, int coloff, const float* __restrict__ nw,
    const float* __restrict__ cosT, const float* __restrict__ sinT,
    const int* __restrict__ pos, float* __restrict__ outf,
    __half* __restrict__ outh, float hscale, int NH, int Tout, int toff)
{
    int idx = blockIdx.x;
    int h  = idx % NH;
    int bt = idx / NH;
    int t  = bt % Tt;
    int b  = bt / Tt;
    int d  = threadIdx.x;

    __shared__ float zn[128];
    __shared__ float red[4];

    float z = raw[(size_t)bt * 3072 + coloff + h * HD + d];
    float ss = z * z;
    #pragma unroll
    for (int o = 16; o; o >>= 1) ss += __shfl_xor_sync(0xffffffffu, ss, o);
    if ((d & 31) == 0) red[d >> 5] = ss;
    __syncthreads();
    float tot = red[0] + red[1] + red[2] + red[3];
    float r = rsqrtf(tot * (1.0f / 128.0f) + 1e-6f);
    float v = z * r * nw[d];
    zn[d] = v;
    __syncthreads();

    int p = pos[bt];
    float c = cosT[p * HD + d];
    float s = sinT[p * HD + d];
    float rot = (d < 64) ? -zn[d + 64] : zn[d - 64];
    float o = fmaf(v, c, rot * s);
    size_t oi = (((size_t)b * NH + h) * Tout + (toff + t)) * HD + d;
    if (outf) outf[oi] = o;
    if (outh) outh[oi] = __float2half_rn(o * hscale);
}

// V scatter: exact fp32 into v_full output
__global__ __launch_bounds__(256) void scatter_v_kernel(
    const float* __restrict__ qkv, float* __restrict__ vf)
{
    int i = blockIdx.x * blockDim.x + threadIdx.x;
    const int n = Bb * Tt * Gg * HD;
    if (i >= n) return;
    int d = i & 127;
    int g = (i >> 7) & 3;
    int t = (i >> 9) % Tt;
    int b = i / (HD * Gg * Tt);
    int bt = b * Tt + t;
    vf[(((size_t)(b * Gg + g)) * SS + CACHEN + t) * HD + d] =
        qkv[(size_t)bt * 3072 + 2560 + g * HD + d];
}

// Cache copy: exact fp32 + optional fp16
__global__ __launch_bounds__(256) void copy_cache_kernel(
    const float4* __restrict__ src, float4* __restrict__ dst,
    uint2* __restrict__ dsth)
{
    int i = blockIdx.x * blockDim.x + threadIdx.x;
    const int per = CACHEN * HD / 4;
    const int n4  = Bb * Gg * per;
    if (i >= n4) return;
    int bg = i / per, r = i % per;
    size_t oi = (size_t)bg * (SS * HD / 4) + r;
    float4 v = src[i];
    dst[oi] = v;
    if (dsth) dsth[oi] = make_uint2(ph2(v.x, v.y), ph2(v.z, v.w));
}

// ---------------------------------------------------------------------------
// fp16 flash attention. grid=(T/128, H, B), 128 threads = 4 warps, each warp
// owns 32 query rows (two 16-row m-groups sharing K/V fragment loads -> 1.76x
// fewer smem bytes per MMA; smem crossbar was the co-limiter at 8 warps).
// 114688B smem, 2 CTAs/SM. Mask via u64 bitmask LDG.
// ---------------------------------------------------------------------------
__global__ __launch_bounds__(128, 2) void attn_h(
    const __half* __restrict__ qh, const __half* __restrict__ kh,
    const __half* __restrict__ vh, const unsigned long long* __restrict__ mbits,
    __half* __restrict__ ctxh)
{
    extern __shared__ unsigned sm[];
    unsigned* Qs = sm;                           // [128][72] words
    unsigned* Ks = sm + 128 * 72;                // 2 x [64][72]
    unsigned* Vs = sm + 128 * 72 + 2 * 64 * 72;  // 2 x [128][40]
    const int KSTG = 64 * 72, VSTG = 128 * 40;

    int qt = blockIdx.x, h = blockIdx.y, b = blockIdx.z;
    int gh = h >> 2;
    int tid = threadIdx.x, lane = tid & 31, wq = tid >> 5;
    int g = lane >> 2, tg = lane & 3;

    const __half* kb = kh + ((size_t)b * Gg + gh) * SS * HD;
    const __half* vb = vh + ((size_t)b * Gg + gh) * (size_t)HD * SS;
    const unsigned long long* mb = mbits + ((size_t)b * Tt + qt * 128) * 64;

    // Q tile: 128 rows x 128 halves, stride 72 words
    {
        const __half* qbase = qh + (((size_t)b * Hh + h) * Tt + qt * 128) * HD;
        #pragma unroll
        for (int t = 0; t < 16; t++) {
            int c = tid + (t << 7);
            int row = c >> 4, ch = c & 15;
            unsigned dq = (unsigned)__cvta_generic_to_shared(
                &Qs[row * 72 + ch * 4]);
            CPASYNC16(dq, qbase + (size_t)row * HD + ch * 8);
        }
    }

    auto load_stage = [&](int ti, int s) {
        #pragma unroll
        for (int t = 0; t < 8; t++) {
            int c = tid + (t << 7);
            int krow = c >> 4, kch = c & 15;
            unsigned dk = (unsigned)__cvta_generic_to_shared(
                &Ks[s * KSTG + krow * 72 + kch * 4]);
            CPASYNC16(dk, kb + (size_t)(ti * 64 + krow) * HD + kch * 8);
            int vrow = c >> 3, vch = c & 7;
            unsigned dv = (unsigned)__cvta_generic_to_shared(
                &Vs[s * VSTG + vrow * 40 + vch * 4]);
            CPASYNC16(dv, vb + (size_t)vrow * SS + ti * 64 + vch * 8);
        }
        asm volatile("cp.async.commit_group;\n");
    };

    // two m-groups per warp: rows qrow+[0,16) and qrow+[16,32)
    float oacc[2][16][4];
    #pragma unroll
    for (int mg = 0; mg < 2; mg++)
        #pragma unroll
        for (int nt = 0; nt < 16; nt++)
            #pragma unroll
            for (int e = 0; e < 4; e++) oacc[mg][nt][e] = 0.0f;
    float mr[2][2] = {{-1e30f, -1e30f}, {-1e30f, -1e30f}};
    float lr[2][2] = {{0.0f, 0.0f}, {0.0f, 0.0f}};
    int qrow = wq * 32;

    load_stage(0, 0);

    const int NT = SS / 64;
    for (int ti = 0; ti < NT; ti++) {
        unsigned long long mbits4[2][2];
        #pragma unroll
        for (int mg = 0; mg < 2; mg++) {
            mbits4[mg][0] = mb[(size_t)(qrow + mg * 16 + g) * 64 + ti];
            mbits4[mg][1] = mb[(size_t)(qrow + mg * 16 + g + 8) * 64 + ti];
        }

        if (ti + 1 < NT) {
            load_stage(ti + 1, (ti + 1) & 1);
            asm volatile("cp.async.wait_group 1;\n");
        } else {
            asm volatile("cp.async.wait_group 0;\n");
        }
        __syncthreads();

        const unsigned* Kb = Ks + (ti & 1) * KSTG;
        const unsigned* Vb = Vs + (ti & 1) * VSTG;

        // S = Q K^T : 8 k16 steps; K fragments shared across both m-groups
        float sacc[2][8][4];
        #pragma unroll
        for (int mg = 0; mg < 2; mg++)
            #pragma unroll
            for (int nt = 0; nt < 8; nt++)
                #pragma unroll
                for (int e = 0; e < 4; e++) sacc[mg][nt][e] = 0.0f;

        #pragma unroll
        for (int ks = 0; ks < 8; ks++) {
            uint2 q0lo = *(const uint2*)&Qs[(qrow + g) * 72 + ks * 8 + 2 * tg];
            uint2 q0hi = *(const uint2*)&Qs[(qrow + g + 8) * 72 + ks * 8 + 2 * tg];
            uint2 q1lo = *(const uint2*)&Qs[(qrow + 16 + g) * 72 + ks * 8 + 2 * tg];
            uint2 q1hi = *(const uint2*)&Qs[(qrow + 24 + g) * 72 + ks * 8 + 2 * tg];
            #pragma unroll
            for (int nt = 0; nt < 8; nt++) {
                uint2 kk = *(const uint2*)&Kb[(nt * 8 + g) * 72 + ks * 8 + 2 * tg];
                mma16(sacc[0][nt], q0lo.x, q0hi.x, q0lo.y, q0hi.y, kk.x, kk.y);
                mma16(sacc[1][nt], q1lo.x, q1hi.x, q1lo.y, q1hi.y, kk.x, kk.y);
            }
        }

        // mask + online softmax per m-group
        float al[2][2];
        float p[2][8][4];
        #pragma unroll
        for (int mg = 0; mg < 2; mg++) {
            #pragma unroll
            for (int nt = 0; nt < 8; nt++) {
                int sh = nt * 8 + 2 * tg;
                if ((mbits4[mg][0] >> sh) & 1)       sacc[mg][nt][0] = -1e30f;
                if ((mbits4[mg][0] >> (sh + 1)) & 1) sacc[mg][nt][1] = -1e30f;
                if ((mbits4[mg][1] >> sh) & 1)       sacc[mg][nt][2] = -1e30f;
                if ((mbits4[mg][1] >> (sh + 1)) & 1) sacc[mg][nt][3] = -1e30f;
            }

            float mx0 = -1e30f, mx1 = -1e30f;
            #pragma unroll
            for (int nt = 0; nt < 8; nt++) {
                mx0 = fmaxf(mx0, fmaxf(sacc[mg][nt][0], sacc[mg][nt][1]));
                mx1 = fmaxf(mx1, fmaxf(sacc[mg][nt][2], sacc[mg][nt][3]));
            }
            mx0 = fmaxf(mx0, __shfl_xor_sync(0xffffffffu, mx0, 1));
            mx0 = fmaxf(mx0, __shfl_xor_sync(0xffffffffu, mx0, 2));
            mx1 = fmaxf(mx1, __shfl_xor_sync(0xffffffffu, mx1, 1));
            mx1 = fmaxf(mx1, __shfl_xor_sync(0xffffffffu, mx1, 2));
            float mn0 = fmaxf(mr[mg][0], mx0), mn1 = fmaxf(mr[mg][1], mx1);
            al[mg][0] = __expf(mr[mg][0] - mn0);
            al[mg][1] = __expf(mr[mg][1] - mn1);
            mr[mg][0] = mn0; mr[mg][1] = mn1;

            float rs0 = 0.0f, rs1 = 0.0f;
            #pragma unroll
            for (int nt = 0; nt < 8; nt++) {
                p[mg][nt][0] = __expf(sacc[mg][nt][0] - mn0);
                p[mg][nt][1] = __expf(sacc[mg][nt][1] - mn0);
                p[mg][nt][2] = __expf(sacc[mg][nt][2] - mn1);
                p[mg][nt][3] = __expf(sacc[mg][nt][3] - mn1);
                rs0 += p[mg][nt][0] + p[mg][nt][1];
                rs1 += p[mg][nt][2] + p[mg][nt][3];
            }
            rs0 += __shfl_xor_sync(0xffffffffu, rs0, 1);
            rs0 += __shfl_xor_sync(0xffffffffu, rs0, 2);
            rs1 += __shfl_xor_sync(0xffffffffu, rs1, 1);
            rs1 += __shfl_xor_sync(0xffffffffu, rs1, 2);
            lr[mg][0] = lr[mg][0] * al[mg][0] + rs0;
            lr[mg][1] = lr[mg][1] * al[mg][1] + rs1;

            #pragma unroll
            for (int nt = 0; nt < 16; nt++) {
                oacc[mg][nt][0] *= al[mg][0]; oacc[mg][nt][1] *= al[mg][0];
                oacc[mg][nt][2] *= al[mg][1]; oacc[mg][nt][3] *= al[mg][1];
            }
        }

        // PV: 4 k16 steps over 64 keys; V fragments shared across m-groups
        #pragma unroll
        for (int w = 0; w < 4; w++) {
            unsigned a0[2], a1[2], a2[2], a3[2];
            #pragma unroll
            for (int mg = 0; mg < 2; mg++) {
                a0[mg] = ph2(p[mg][2*w][0],   p[mg][2*w][1]);
                a1[mg] = ph2(p[mg][2*w][2],   p[mg][2*w][3]);
                a2[mg] = ph2(p[mg][2*w+1][0], p[mg][2*w+1][1]);
                a3[mg] = ph2(p[mg][2*w+1][2], p[mg][2*w+1][3]);
            }
            #pragma unroll
            for (int nt = 0; nt < 16; nt++) {
                uint2 vv = *(const uint2*)&Vb[(nt * 8 + g) * 40 + w * 8 + 2 * tg];
                mma16(oacc[0][nt], a0[0], a1[0], a2[0], a3[0], vv.x, vv.y);
                mma16(oacc[1][nt], a0[1], a1[1], a2[1], a3[1], vv.x, vv.y);
            }
        }
        __syncthreads();
    }

    // epilogue: ctx as fp16 (half2 stores), two m-groups
    #pragma unroll
    for (int mg = 0; mg < 2; mg++) {
        float il0 = 1.0f / lr[mg][0], il1 = 1.0f / lr[mg][1];
        int tok0 = qt * 128 + qrow + mg * 16 + g;
        #pragma unroll
        for (int nt = 0; nt < 16; nt++) {
            int d = nt * 8 + 2 * tg;
            unsigned w0 = ph2(oacc[mg][nt][0] * il0, oacc[mg][nt][1] * il0);
            unsigned w1 = ph2(oacc[mg][nt][2] * il1, oacc[mg][nt][3] * il1);
            *(unsigned*)&ctxh[(((size_t)b * Tt + tok0) * Hh + h) * HD + d] = w0;
            *(unsigned*)&ctxh[(((size_t)b * Tt + tok0 + 8) * Hh + h) * HD + d] = w1;
        }
    }
}

// ---------------------------------------------------------------------------
extern "C" void kernel_launch(void* const* d_in, const int* in_sizes, int n_in,
                              void* d_out, int out_size)
{
    const float*   x       = (const float*)d_in[0];
    const uint8_t* mask    = (const uint8_t*)d_in[1];
    const float*   cosT    = (const float*)d_in[2];
    const float*   sinT    = (const float*)d_in[3];
    const int*     pos     = (const int*)d_in[4];
    const float*   cache_k = (const float*)d_in[5];
    const float*   cache_v = (const float*)d_in[6];
    const float*   q_w     = (const float*)d_in[7];
    const float*   k_w     = (const float*)d_in[8];
    const float*   v_w     = (const float*)d_in[9];
    const float*   o_w     = (const float*)d_in[10];
    const float*   qn_w    = (const float*)d_in[11];
    const float*   kn_w    = (const float*)d_in[12];

    float* out_ctx = (float*)d_out;
    float* out_k   = out_ctx + (size_t)Bb * Tt * Hh * HD;
    float* out_v   = out_k   + (size_t)Bb * Gg * SS * HD;

    __half *xh, *wqkvh, *owh, *qhp, *ctxh, *khp, *vhp;
    float *qkv;
    unsigned long long *mbp;
    cudaGetSymbolAddress((void**)&xh,    g_xh);
    cudaGetSymbolAddress((void**)&wqkvh, g_wqkvh);
    cudaGetSymbolAddress((void**)&owh,   g_owh);
    cudaGetSymbolAddress((void**)&qkv,   g_qkv);
    cudaGetSymbolAddress((void**)&qhp,   g_qh);
    cudaGetSymbolAddress((void**)&ctxh,  g_ctxh);
    cudaGetSymbolAddress((void**)&khp,   g_kh);
    cudaGetSymbolAddress((void**)&vhp,   g_vh);
    cudaGetSymbolAddress((void**)&mbp,   g_mb);

    // Fork side stream for independent copy/convert work (round-10 topology).
    cudaEventRecord(g_res.e0, 0);
    cudaStreamWaitEvent(g_res.s2, g_res.e0, 0);
    {
        int n4 = Bb * Gg * CACHEN * HD / 4;
        int blocks = (n4 + 255) / 256;
        copy_cache_kernel<<<blocks, 256, 0, g_res.s2>>>(
            (const float4*)cache_k, (float4*)out_k, (uint2*)khp);
        copy_cache_kernel<<<blocks, 256, 0, g_res.s2>>>(
            (const float4*)cache_v, (float4*)out_v, nullptr);
        transpose_ow_kernel<<<dim3(64, 64), 256, 0, g_res.s2>>>(o_w, owh);
        int nm = Bb * Tt * 64;
        pack_mask_kernel<<<(nm + 255) / 256, 256, 0, g_res.s2>>>(mask, mbp);
    }
    cudaEventRecord(g_res.e2, g_res.s2);

    // Main stream: projection chain.
    {
        int n4x = 2048 * 2048 / 4;
        conv_x_kernel<<<(n4x + 255) / 256, 256>>>((const float4*)x, (uint2*)xh, n4x);
        pack_wqkvT_kernel<<<dim3(32, 48), 256>>>(q_w, k_w, v_w, wqkvh);
    }

    // fused QKV projection: [2048,2048] @ [3072,2048]^T, fp16 mma
    size_t gsmem = (size_t)(4 * 128 * 40) * 4;
    cudaFuncSetAttribute(gemm_h, cudaFuncAttributeMaxDynamicSharedMemorySize, (int)gsmem);
    gemm_h<<<dim3(24, 16), 256, gsmem>>>(xh, wqkvh, qkv, 2048, 3072, 2048);

    // fp16 transposed+permuted V scratch straight from sources (main stream)
    transpose_v_kernel<<<dim3(SS / 32, HD / 32, Bb * Gg), 256>>>(cache_v, qkv, vhp);

    // RMSNorm + RoPE; Q -> fp16 scratch (pre-scaled); K -> fp32 out + fp16 scratch
    const float scale = 0.08838834764831845f;   // 1/sqrt(128)
    norm_rope_kernel<<<Bb * Tt * Hh, 128>>>(qkv, 0,    qn_w, cosT, sinT, pos,
                                            nullptr, qhp, scale, Hh, Tt, 0);
    norm_rope_kernel<<<Bb * Tt * Gg, 128>>>(qkv, 2048, kn_w, cosT, sinT, pos,
                                            out_k, khp, 1.0f, Gg, SS, CACHEN);

    // V into v_full (exact fp32)
    {
        int n = Bb * Tt * Gg * HD;
        scatter_v_kernel<<<(n + 255) / 256, 256>>>(qkv, out_v);
    }

    // Join: attention needs khp's cache half + mask bits; O-GEMM needs owh.
    cudaStreamWaitEvent(0, g_res.e2, 0);

    // attention (fp16 mma, 4 warps x 32 rows, 2 CTAs/SM, bitmask mask path)
    size_t smem = (size_t)(128 * 72 + 2 * 64 * 72 + 2 * 128 * 40) * 4;  // 114688
    cudaFuncSetAttribute(attn_h, cudaFuncAttributeMaxDynamicSharedMemorySize, (int)smem);
    attn_h<<<dim3(Tt / 128, Hh, Bb), 128, smem>>>(qhp, khp, vhp, mbp, ctxh);

    // output projection: [2048,2048] @ [2048,2048]^T, fp16 mma
    gemm_h<<<dim3(16, 16), 256, gsmem>>>(ctxh, owh, out_ctx, 2048, 2048, 2048);
}

// round 14
// speedup vs baseline: 1.0698x; 1.0698x over previous
#include <cuda_runtime.h>
#include <cuda_fp16.h>
#include <stdint.h>

#define Bb 4
#define Tt 512
#define Hh 16
#define Gg 4
#define HD 128
#define CACHEN 3584
#define SS 4096

// Scratch (static device arrays; no allocation allowed)
__device__ __half g_xh   [2048*2048];    // fp16 x               [M,K] K-major
__device__ __half g_wqkvh[3072*2048];    // fp16 qkv weights     [N,K] K-major
__device__ __half g_owh  [2048*2048];    // fp16 o_w             [N,K] K-major
__device__ float  g_qkv  [2048*3072];    // fused projection output (fp32)
__device__ __half g_qh   [Bb*Hh*Tt*HD];  // fp16 Q (pre-scaled) [B,H,T,HD]
__device__ __half g_ctxh [Bb*Tt*Hh*HD];  // fp16 ctx [B,T,H*HD]
__device__ __half g_kh   [Bb*Gg*SS*HD];  // fp16 k_full [B,G,S,HD]
__device__ __half g_vh   [Bb*Gg*HD*SS];  // fp16 v_full transposed [B,G,HD,S], keys permuted in 16-groups
__device__ unsigned long long g_mb[Bb*Tt*64]; // mask bitmask: [b*T + t][tile]

// Side-stream resources, created once at program load (before any capture).
struct GpuRes {
    cudaStream_t s2;
    cudaEvent_t e0, e1, e2;
    GpuRes() {
        cudaStreamCreateWithFlags(&s2, cudaStreamNonBlocking);
        cudaEventCreateWithFlags(&e0, cudaEventDisableTiming);
        cudaEventCreateWithFlags(&e1, cudaEventDisableTiming);
        cudaEventCreateWithFlags(&e2, cudaEventDisableTiming);
    }
};
static GpuRes g_res;

// pack two floats into half2 (lo, hi)
__device__ __forceinline__ unsigned ph2(float lo, float hi) {
    unsigned r;
    asm("cvt.rn.f16x2.f32 %0, %1, %2;" : "=r"(r) : "f"(hi), "f"(lo));
    return r;
}

__device__ __forceinline__ void mma16(float* c,
    unsigned a0, unsigned a1, unsigned a2, unsigned a3,
    unsigned b0, unsigned b1)
{
    asm volatile(
        "mma.sync.aligned.m16n8k16.row.col.f32.f16.f16.f32 "
        "{%0,%1,%2,%3}, {%4,%5,%6,%7}, {%8,%9}, {%0,%1,%2,%3};"
        : "+f"(c[0]), "+f"(c[1]), "+f"(c[2]), "+f"(c[3])
        : "r"(a0), "r"(a1), "r"(a2), "r"(a3), "r"(b0), "r"(b1));
}

#define CPASYNC16(dst_sm, src_gm) \
    asm volatile("cp.async.cg.shared.global [%0], [%1], 16;\n" \
                 :: "r"(dst_sm), "l"(src_gm))

// key permutation within a 16-group so PV B-fragments are contiguous uint2
__device__ __forceinline__ int perm16(int s) {
    return ((s >> 1) & 3) * 4 + ((s >> 3) & 1) * 2 + (s & 1);
}

// ---------------------------------------------------------------------------
// Prep kernels
// ---------------------------------------------------------------------------
__global__ __launch_bounds__(256) void conv_x_kernel(
    const float4* __restrict__ src, uint2* __restrict__ dst, int n4)
{
    int i = blockIdx.x * blockDim.x + threadIdx.x;
    if (i >= n4) return;
    float4 v = src[i];
    dst[i] = make_uint2(ph2(v.x, v.y), ph2(v.z, v.w));
}

// Pack mask bytes into per-tile u64 bitmasks: out[row][tile], row = b*T+t.
__global__ __launch_bounds__(256) void pack_mask_kernel(
    const uint8_t* __restrict__ mask, unsigned long long* __restrict__ out)
{
    int i = blockIdx.x * blockDim.x + threadIdx.x;
    if (i >= Bb * Tt * 64) return;
    int tile = i & 63, row = i >> 6;
    const unsigned long long* src = (const unsigned long long*)
        (mask + (size_t)row * SS + tile * 64);
    unsigned long long bits = 0;
    #pragma unroll
    for (int c = 0; c < 8; c++) {
        unsigned long long w = src[c];
        #pragma unroll
        for (int j = 0; j < 8; j++)
            if ((w >> (8 * j)) & 0xFFull)
                bits |= 1ull << (c * 8 + j);
    }
    out[i] = bits;
}

// Transposed qkv weight pack (vectorized): dst[n][k] = fp16(w[k][n]).
__global__ __launch_bounds__(256) void pack_wqkvT_kernel(
    const float* __restrict__ qw, const float* __restrict__ kw,
    const float* __restrict__ vw, __half* __restrict__ dst)
{
    __shared__ float tile[64][65];
    int k0 = blockIdx.x << 6;
    int n0 = blockIdx.y << 6;
    const float* src; int ncol, nbase;
    if (n0 < 2048)      { src = qw; ncol = 2048; nbase = 0; }
    else if (n0 < 2560) { src = kw; ncol = 512;  nbase = 2048; }
    else                { src = vw; ncol = 512;  nbase = 2560; }

    #pragma unroll
    for (int t = 0; t < 4; t++) {
        int idx = threadIdx.x + (t << 8);
        int r = idx >> 4, c4 = (idx & 15) << 2;
        float4 v = *(const float4*)&src[(size_t)(k0 + r) * ncol + (n0 - nbase) + c4];
        tile[r][c4] = v.x; tile[r][c4 + 1] = v.y;
        tile[r][c4 + 2] = v.z; tile[r][c4 + 3] = v.w;
    }
    __syncthreads();
    #pragma unroll
    for (int t = 0; t < 2; t++) {
        int idx = threadIdx.x + (t << 8);
        int n = idx >> 3, c8 = idx & 7;
        __half h[8];
        #pragma unroll
        for (int j = 0; j < 8; j++)
            h[j] = __float2half_rn(tile[c8 * 8 + j][n]);
        *(uint4*)&dst[(size_t)(n0 + n) * 2048 + k0 + c8 * 8] = *(uint4*)h;
    }
}

// o_w transpose: dst[n][k] = fp16(src[k][n]), 2048x2048 (side stream, hidden)
__global__ __launch_bounds__(256) void transpose_ow_kernel(
    const float* __restrict__ src, __half* __restrict__ dst)
{
    __shared__ float tile[32][33];
    int k0 = blockIdx.x << 5, n0 = blockIdx.y << 5;
    int tx = threadIdx.x & 31, ty = threadIdx.x >> 5;
    #pragma unroll
    for (int r = 0; r < 32; r += 8)
        tile[ty + r][tx] = src[(size_t)(k0 + ty + r) * 2048 + n0 + tx];
    __syncthreads();
    #pragma unroll
    for (int r = 0; r < 32; r += 8)
        dst[(size_t)(n0 + ty + r) * 2048 + k0 + tx] =
            __float2half_rn(tile[tx][ty + r]);
}

// V: transpose + fp16 + key permutation into [bg][d][s'], sources direct.
__global__ __launch_bounds__(256) void transpose_v_kernel(
    const float* __restrict__ cache_v, const float* __restrict__ qkv,
    __half* __restrict__ dst)
{
    __shared__ float tile[32][33];
    int bg = blockIdx.z;
    int b = bg >> 2, g = bg & 3;
    int s0 = blockIdx.x << 5, d0 = blockIdx.y << 5;
    int tx = threadIdx.x & 31, ty = threadIdx.x >> 5;

    if (s0 < CACHEN) {
        const float* s = cache_v + (size_t)bg * CACHEN * HD;
        #pragma unroll
        for (int r = 0; r < 32; r += 8)
            tile[ty + r][tx] = s[(size_t)(s0 + ty + r) * HD + d0 + tx];
    } else {
        #pragma unroll
        for (int r = 0; r < 32; r += 8) {
            int t = s0 + ty + r - CACHEN;
            tile[ty + r][tx] =
                qkv[(size_t)(b * Tt + t) * 3072 + 2560 + g * HD + d0 + tx];
        }
    }
    __syncthreads();
    __half* d = dst + (size_t)bg * HD * SS;
    int sp = s0 + (tx & ~15) + perm16(tx & 15);
    #pragma unroll
    for (int r = 0; r < 32; r += 8)
        d[(size_t)(d0 + ty + r) * SS + sp] = __float2half_rn(tile[tx][ty + r]);
}

// ---------------------------------------------------------------------------
// fp16 GEMM (unchanged).
// ---------------------------------------------------------------------------
__global__ __launch_bounds__(256, 2) void gemm_h(
    const __half* __restrict__ A, const __half* __restrict__ Bm,
    float* __restrict__ C, int M, int N, int K)
{
    extern __shared__ unsigned sm[];
    unsigned* As = sm;
    unsigned* Bs = sm + 2 * 128 * 40;
    const int STG = 128 * 40;

    int tid = threadIdx.x, lane = tid & 31, warp = tid >> 5;
    int g = lane >> 2, tg = lane & 3;
    int m0 = blockIdx.y << 7, n0 = blockIdx.x << 7;
    int wm = (warp >> 2) << 6, wn = (warp & 3) << 5;

    float acc[4][4][4];
    #pragma unroll
    for (int i = 0; i < 4; i++)
        #pragma unroll
        for (int j = 0; j < 4; j++)
            #pragma unroll
            for (int e = 0; e < 4; e++) acc[i][j][e] = 0.0f;

    auto load_stage = [&](int it) {
        int s = it & 1;
        int k0 = it << 6;
        #pragma unroll
        for (int t = 0; t < 4; t++) {
            int c = tid + (t << 8);
            int row = c >> 3, ch = c & 7;
            unsigned da = (unsigned)__cvta_generic_to_shared(
                &As[s * STG + row * 40 + ch * 4]);
            CPASYNC16(da, A + (size_t)(m0 + row) * K + k0 + ch * 8);
            unsigned db = (unsigned)__cvta_generic_to_shared(
                &Bs[s * STG + row * 40 + ch * 4]);
            CPASYNC16(db, Bm + (size_t)(n0 + row) * K + k0 + ch * 8);
        }
        asm volatile("cp.async.commit_group;\n");
    };

    int niter = K >> 6;
    load_stage(0);

    for (int it = 0; it < niter; it++) {
        if (it + 1 < niter) {
            load_stage(it + 1);
            asm volatile("cp.async.wait_group 1;\n");
        } else {
            asm volatile("cp.async.wait_group 0;\n");
        }
        __syncthreads();

        const unsigned* Ab = As + (it & 1) * STG;
        const unsigned* Bbuf = Bs + (it & 1) * STG;
        #pragma unroll
        for (int ks = 0; ks < 4; ks++) {
            uint2 alo[4], ahi[4];
            #pragma unroll
            for (int mt = 0; mt < 4; mt++) {
                int r = wm + mt * 16;
                alo[mt] = *(const uint2*)&Ab[(r + g) * 40 + ks * 8 + 2 * tg];
                ahi[mt] = *(const uint2*)&Ab[(r + g + 8) * 40 + ks * 8 + 2 * tg];
            }
            #pragma unroll
            for (int nt = 0; nt < 4; nt++) {
                uint2 bb = *(const uint2*)&Bbuf[(wn + nt * 8 + g) * 40 + ks * 8 + 2 * tg];
                #pragma unroll
                for (int mt = 0; mt < 4; mt++)
                    mma16(acc[mt][nt], alo[mt].x, ahi[mt].x, alo[mt].y, ahi[mt].y,
                          bb.x, bb.y);
            }
        }
        __syncthreads();
    }

    #pragma unroll
    for (int mt = 0; mt < 4; mt++)
        #pragma unroll
        for (int nt = 0; nt < 4; nt++) {
            int r0 = m0 + wm + mt * 16 + g;
            int c  = n0 + wn + nt * 8 + 2 * tg;
            float2 v0 = make_float2(acc[mt][nt][0], acc[mt][nt][1]);
            float2 v1 = make_float2(acc[mt][nt][2], acc[mt][nt][3]);
            *(float2*)&C[(size_t)r0 * N + c] = v0;
            *(float2*)&C[(size_t)(r0 + 8) * N + c] = v1;
        }
}

// ---------------------------------------------------------------------------
// Fused per-head RMSNorm + RoPE; fp32 out (nullable) + fp16 out (nullable).
// ---------------------------------------------------------------------------
__global__ __launch_bounds__(128) void norm_rope_kernel(
    const float* __restrict__ raw, int coloff, const float* __restrict__ nw,
    const float* __restrict__ cosT, const float* __restrict__ sinT,
    const int* __restrict__ pos, float* __restrict__ outf,
    __half* __restrict__ outh, float hscale, int NH, int Tout, int toff)
{
    int idx = blockIdx.x;
    int h  = idx % NH;
    int bt = idx / NH;
    int t  = bt % Tt;
    int b  = bt / Tt;
    int d  = threadIdx.x;

    __shared__ float zn[128];
    __shared__ float red[4];

    float z = raw[(size_t)bt * 3072 + coloff + h * HD + d];
    float ss = z * z;
    #pragma unroll
    for (int o = 16; o; o >>= 1) ss += __shfl_xor_sync(0xffffffffu, ss, o);
    if ((d & 31) == 0) red[d >> 5] = ss;
    __syncthreads();
    float tot = red[0] + red[1] + red[2] + red[3];
    float r = rsqrtf(tot * (1.0f / 128.0f) + 1e-6f);
    float v = z * r * nw[d];
    zn[d] = v;
    __syncthreads();

    int p = pos[bt];
    float c = cosT[p * HD + d];
    float s = sinT[p * HD + d];
    float rot = (d < 64) ? -zn[d + 64] : zn[d - 64];
    float o = fmaf(v, c, rot * s);
    size_t oi = (((size_t)b * NH + h) * Tout + (toff + t)) * HD + d;
    if (outf) outf[oi] = o;
    if (outh) outh[oi] = __float2half_rn(o * hscale);
}

// V scatter: exact fp32 into v_full output
__global__ __launch_bounds__(256) void scatter_v_kernel(
    const float* __restrict__ qkv, float* __restrict__ vf)
{
    int i = blockIdx.x * blockDim.x + threadIdx.x;
    const int n = Bb * Tt * Gg * HD;
    if (i >= n) return;
    int d = i & 127;
    int g = (i >> 7) & 3;
    int t = (i >> 9) % Tt;
    int b = i / (HD * Gg * Tt);
    int bt = b * Tt + t;
    vf[(((size_t)(b * Gg + g)) * SS + CACHEN + t) * HD + d] =
        qkv[(size_t)bt * 3072 + 2560 + g * HD + d];
}

// Cache copy: exact fp32 + optional fp16
__global__ __launch_bounds__(256) void copy_cache_kernel(
    const float4* __restrict__ src, float4* __restrict__ dst,
    uint2* __restrict__ dsth)
{
    int i = blockIdx.x * blockDim.x + threadIdx.x;
    const int per = CACHEN * HD / 4;
    const int n4  = Bb * Gg * per;
    if (i >= n4) return;
    int bg = i / per, r = i % per;
    size_t oi = (size_t)bg * (SS * HD / 4) + r;
    float4 v = src[i];
    dst[oi] = v;
    if (dsth) dsth[oi] = make_uint2(ph2(v.x, v.y), ph2(v.z, v.w));
}

// ---------------------------------------------------------------------------
// fp16 flash attention (round-12 version: 8 warps, 2 CTAs/SM, bitmask mask).
// ---------------------------------------------------------------------------
__global__ __launch_bounds__(256, 2) void attn_h(
    const __half* __restrict__ qh, const __half* __restrict__ kh,
    const __half* __restrict__ vh, const unsigned long long* __restrict__ mbits,
    __half* __restrict__ ctxh)
{
    extern __shared__ unsigned sm[];
    unsigned* Qs = sm;                           // [128][72] words
    unsigned* Ks = sm + 128 * 72;                // 2 x [64][72]
    unsigned* Vs = sm + 128 * 72 + 2 * 64 * 72;  // 2 x [128][40]
    const int KSTG = 64 * 72, VSTG = 128 * 40;

    int qt = blockIdx.x, h = blockIdx.y, b = blockIdx.z;
    int gh = h >> 2;
    int tid = threadIdx.x, lane = tid & 31, wq = tid >> 5;
    int g = lane >> 2, tg = lane & 3;

    const __half* kb = kh + ((size_t)b * Gg + gh) * SS * HD;
    const __half* vb = vh + ((size_t)b * Gg + gh) * (size_t)HD * SS;
    const unsigned long long* mb = mbits + ((size_t)b * Tt + qt * 128) * 64;

    {
        const __half* qbase = qh + (((size_t)b * Hh + h) * Tt + qt * 128) * HD;
        #pragma unroll
        for (int t = 0; t < 8; t++) {
            int c = tid + (t << 8);
            int row = c >> 4, ch = c & 15;
            unsigned dq = (unsigned)__cvta_generic_to_shared(
                &Qs[row * 72 + ch * 4]);
            CPASYNC16(dq, qbase + (size_t)row * HD + ch * 8);
        }
    }

    auto load_stage = [&](int ti, int s) {
        #pragma unroll
        for (int t = 0; t < 4; t++) {
            int c = tid + (t << 8);
            int krow = c >> 4, kch = c & 15;
            unsigned dk = (unsigned)__cvta_generic_to_shared(
                &Ks[s * KSTG + krow * 72 + kch * 4]);
            CPASYNC16(dk, kb + (size_t)(ti * 64 + krow) * HD + kch * 8);
            int vrow = c >> 3, vch = c & 7;
            unsigned dv = (unsigned)__cvta_generic_to_shared(
                &Vs[s * VSTG + vrow * 40 + vch * 4]);
            CPASYNC16(dv, vb + (size_t)vrow * SS + ti * 64 + vch * 8);
        }
        asm volatile("cp.async.commit_group;\n");
    };

    float oacc[16][4];
    #pragma unroll
    for (int nt = 0; nt < 16; nt++)
        #pragma unroll
        for (int e = 0; e < 4; e++) oacc[nt][e] = 0.0f;
    float m0r = -1e30f, m1r = -1e30f, l0 = 0.0f, l1 = 0.0f;
    int qrow = wq * 16;

    load_stage(0, 0);

    const int NT = SS / 64;
    for (int ti = 0; ti < NT; ti++) {
        unsigned long long mb0 = mb[(size_t)(qrow + g) * 64 + ti];
        unsigned long long mb1 = mb[(size_t)(qrow + g + 8) * 64 + ti];

        if (ti + 1 < NT) {
            load_stage(ti + 1, (ti + 1) & 1);
            asm volatile("cp.async.wait_group 1;\n");
        } else {
            asm volatile("cp.async.wait_group 0;\n");
        }
        __syncthreads();

        const unsigned* Kb = Ks + (ti & 1) * KSTG;
        const unsigned* Vb = Vs + (ti & 1) * VSTG;

        float sacc[8][4];
        #pragma unroll
        for (int nt = 0; nt < 8; nt++)
            #pragma unroll
            for (int e = 0; e < 4; e++) sacc[nt][e] = 0.0f;

        #pragma unroll
        for (int ks = 0; ks < 8; ks++) {
            uint2 qlo = *(const uint2*)&Qs[(qrow + g) * 72 + ks * 8 + 2 * tg];
            uint2 qhi = *(const uint2*)&Qs[(qrow + g + 8) * 72 + ks * 8 + 2 * tg];
            #pragma unroll
            for (int nt = 0; nt < 8; nt++) {
                uint2 kk = *(const uint2*)&Kb[(nt * 8 + g) * 72 + ks * 8 + 2 * tg];
                mma16(sacc[nt], qlo.x, qhi.x, qlo.y, qhi.y, kk.x, kk.y);
            }
        }

        #pragma unroll
        for (int nt = 0; nt < 8; nt++) {
            int sh = nt * 8 + 2 * tg;
            if ((mb0 >> sh) & 1)       sacc[nt][0] = -1e30f;
            if ((mb0 >> (sh + 1)) & 1) sacc[nt][1] = -1e30f;
            if ((mb1 >> sh) & 1)       sacc[nt][2] = -1e30f;
            if ((mb1 >> (sh + 1)) & 1) sacc[nt][3] = -1e30f;
        }

        float mx0 = -1e30f, mx1 = -1e30f;
        #pragma unroll
        for (int nt = 0; nt < 8; nt++) {
            mx0 = fmaxf(mx0, fmaxf(sacc[nt][0], sacc[nt][1]));
            mx1 = fmaxf(mx1, fmaxf(sacc[nt][2], sacc[nt][3]));
        }
        mx0 = fmaxf(mx0, __shfl_xor_sync(0xffffffffu, mx0, 1));
        mx0 = fmaxf(mx0, __shfl_xor_sync(0xffffffffu, mx0, 2));
        mx1 = fmaxf(mx1, __shfl_xor_sync(0xffffffffu, mx1, 1));
        mx1 = fmaxf(mx1, __shfl_xor_sync(0xffffffffu, mx1, 2));
        float mn0 = fmaxf(m0r, mx0), mn1 = fmaxf(m1r, mx1);
        float al0 = __expf(m0r - mn0), al1 = __expf(m1r - mn1);
        m0r = mn0; m1r = mn1;

        float p[8][4];
        float rs0 = 0.0f, rs1 = 0.0f;
        #pragma unroll
        for (int nt = 0; nt < 8; nt++) {
            p[nt][0] = __expf(sacc[nt][0] - mn0);
            p[nt][1] = __expf(sacc[nt][1] - mn0);
            p[nt][2] = __expf(sacc[nt][2] - mn1);
            p[nt][3] = __expf(sacc[nt][3] - mn1);
            rs0 += p[nt][0] + p[nt][1]; rs1 += p[nt][2] + p[nt][3];
        }
        rs0 += __shfl_xor_sync(0xffffffffu, rs0, 1);
        rs0 += __shfl_xor_sync(0xffffffffu, rs0, 2);
        rs1 += __shfl_xor_sync(0xffffffffu, rs1, 1);
        rs1 += __shfl_xor_sync(0xffffffffu, rs1, 2);
        l0 = l0 * al0 + rs0;
        l1 = l1 * al1 + rs1;

        #pragma unroll
        for (int nt = 0; nt < 16; nt++) {
            oacc[nt][0] *= al0; oacc[nt][1] *= al0;
            oacc[nt][2] *= al1; oacc[nt][3] *= al1;
        }

        #pragma unroll
        for (int w = 0; w < 4; w++) {
            unsigned a0 = ph2(p[2*w][0],   p[2*w][1]);
            unsigned a1 = ph2(p[2*w][2],   p[2*w][3]);
            unsigned a2 = ph2(p[2*w+1][0], p[2*w+1][1]);
            unsigned a3 = ph2(p[2*w+1][2], p[2*w+1][3]);
            #pragma unroll
            for (int nt = 0; nt < 16; nt++) {
                uint2 vv = *(const uint2*)&Vb[(nt * 8 + g) * 40 + w * 8 + 2 * tg];
                mma16(oacc[nt], a0, a1, a2, a3, vv.x, vv.y);
            }
        }
        __syncthreads();
    }

    float il0 = 1.0f / l0, il1 = 1.0f / l1;
    int tok0 = qt * 128 + qrow + g;
    #pragma unroll
    for (int nt = 0; nt < 16; nt++) {
        int d = nt * 8 + 2 * tg;
        unsigned w0 = ph2(oacc[nt][0] * il0, oacc[nt][1] * il0);
        unsigned w1 = ph2(oacc[nt][2] * il1, oacc[nt][3] * il1);
        *(unsigned*)&ctxh[(((size_t)b * Tt + tok0) * Hh + h) * HD + d] = w0;
        *(unsigned*)&ctxh[(((size_t)b * Tt + tok0 + 8) * Hh + h) * HD + d] = w1;
    }
}

// ---------------------------------------------------------------------------
extern "C" void kernel_launch(void* const* d_in, const int* in_sizes, int n_in,
                              void* d_out, int out_size)
{
    const float*   x       = (const float*)d_in[0];
    const uint8_t* mask    = (const uint8_t*)d_in[1];
    const float*   cosT    = (const float*)d_in[2];
    const float*   sinT    = (const float*)d_in[3];
    const int*     pos     = (const int*)d_in[4];
    const float*   cache_k = (const float*)d_in[5];
    const float*   cache_v = (const float*)d_in[6];
    const float*   q_w     = (const float*)d_in[7];
    const float*   k_w     = (const float*)d_in[8];
    const float*   v_w     = (const float*)d_in[9];
    const float*   o_w     = (const float*)d_in[10];
    const float*   qn_w    = (const float*)d_in[11];
    const float*   kn_w    = (const float*)d_in[12];

    float* out_ctx = (float*)d_out;
    float* out_k   = out_ctx + (size_t)Bb * Tt * Hh * HD;
    float* out_v   = out_k   + (size_t)Bb * Gg * SS * HD;

    __half *xh, *wqkvh, *owh, *qhp, *ctxh, *khp, *vhp;
    float *qkv;
    unsigned long long *mbp;
    cudaGetSymbolAddress((void**)&xh,    g_xh);
    cudaGetSymbolAddress((void**)&wqkvh, g_wqkvh);
    cudaGetSymbolAddress((void**)&owh,   g_owh);
    cudaGetSymbolAddress((void**)&qkv,   g_qkv);
    cudaGetSymbolAddress((void**)&qhp,   g_qh);
    cudaGetSymbolAddress((void**)&ctxh,  g_ctxh);
    cudaGetSymbolAddress((void**)&khp,   g_kh);
    cudaGetSymbolAddress((void**)&vhp,   g_vh);
    cudaGetSymbolAddress((void**)&mbp,   g_mb);

    // Fork side stream: weight pack FIRST (main waits on it before the GEMM),
    // then the copy/convert work whose consumer is the attention kernel.
    cudaEventRecord(g_res.e0, 0);
    cudaStreamWaitEvent(g_res.s2, g_res.e0, 0);
    pack_wqkvT_kernel<<<dim3(32, 48), 256, 0, g_res.s2>>>(q_w, k_w, v_w, wqkvh);
    cudaEventRecord(g_res.e1, g_res.s2);
    {
        int n4 = Bb * Gg * CACHEN * HD / 4;
        int blocks = (n4 + 255) / 256;
        copy_cache_kernel<<<blocks, 256, 0, g_res.s2>>>(
            (const float4*)cache_k, (float4*)out_k, (uint2*)khp);
        copy_cache_kernel<<<blocks, 256, 0, g_res.s2>>>(
            (const float4*)cache_v, (float4*)out_v, nullptr);
        transpose_ow_kernel<<<dim3(64, 64), 256, 0, g_res.s2>>>(o_w, owh);
        int nm = Bb * Tt * 64;
        pack_mask_kernel<<<(nm + 255) / 256, 256, 0, g_res.s2>>>(mask, mbp);
    }
    cudaEventRecord(g_res.e2, g_res.s2);

    // Main stream: x conversion (concurrent with the weight pack on s2).
    {
        int n4x = 2048 * 2048 / 4;
        conv_x_kernel<<<(n4x + 255) / 256, 256>>>((const float4*)x, (uint2*)xh, n4x);
    }
    cudaStreamWaitEvent(0, g_res.e1, 0);

    // fused QKV projection: [2048,2048] @ [3072,2048]^T, fp16 mma
    size_t gsmem = (size_t)(4 * 128 * 40) * 4;
    cudaFuncSetAttribute(gemm_h, cudaFuncAttributeMaxDynamicSharedMemorySize, (int)gsmem);
    gemm_h<<<dim3(24, 16), 256, gsmem>>>(xh, wqkvh, qkv, 2048, 3072, 2048);

    // fp16 transposed+permuted V scratch straight from sources (main stream)
    transpose_v_kernel<<<dim3(SS / 32, HD / 32, Bb * Gg), 256>>>(cache_v, qkv, vhp);

    // RMSNorm + RoPE; Q -> fp16 scratch (pre-scaled); K -> fp32 out + fp16 scratch
    const float scale = 0.08838834764831845f;   // 1/sqrt(128)
    norm_rope_kernel<<<Bb * Tt * Hh, 128>>>(qkv, 0,    qn_w, cosT, sinT, pos,
                                            nullptr, qhp, scale, Hh, Tt, 0);
    norm_rope_kernel<<<Bb * Tt * Gg, 128>>>(qkv, 2048, kn_w, cosT, sinT, pos,
                                            out_k, khp, 1.0f, Gg, SS, CACHEN);

    // V into v_full (exact fp32)
    {
        int n = Bb * Tt * Gg * HD;
        scatter_v_kernel<<<(n + 255) / 256, 256>>>(qkv, out_v);
    }

    // Join: attention needs khp's cache half + mask bits; O-GEMM needs owh.
    cudaStreamWaitEvent(0, g_res.e2, 0);

    // attention (fp16 mma, 8 warps, 2 CTAs/SM, bitmask mask path)
    size_t smem = (size_t)(128 * 72 + 2 * 64 * 72 + 2 * 128 * 40) * 4;  // 114688
    cudaFuncSetAttribute(attn_h, cudaFuncAttributeMaxDynamicSharedMemorySize, (int)smem);
    attn_h<<<dim3(Tt / 128, Hh, Bb), 256, smem>>>(qhp, khp, vhp, mbp, ctxh);

    // output projection: [2048,2048] @ [2048,2048]^T, fp16 mma
    gemm_h<<<dim3(16, 16), 256, gsmem>>>(ctxh, owh, out_ctx, 2048, 2048, 2048);
}

// round 15
// speedup vs baseline: 1.0888x; 1.0178x over previous
#include <cuda_runtime.h>
#include <cuda_fp16.h>
#include <stdint.h>

#define Bb 4
#define Tt 512
#define Hh 16
#define Gg 4
#define HD 128
#define CACHEN 3584
#define SS 4096

// Scratch (static device arrays; no allocation allowed)
__device__ __half g_xh   [2048*2048];    // fp16 x               [M,K] K-major
__device__ __half g_wqkvh[3072*2048];    // fp16 qkv weights     [N,K] K-major
__device__ __half g_owh  [2048*2048];    // fp16 o_w             [N,K] K-major
__device__ float  g_qkv  [2048*3072];    // fused projection output (fp32)
__device__ __half g_qh   [Bb*Hh*Tt*HD];  // fp16 Q (pre-scaled) [B,H,T,HD]
__device__ __half g_ctxh [Bb*Tt*Hh*HD];  // fp16 ctx [B,T,H*HD]
__device__ __half g_kh   [Bb*Gg*SS*HD];  // fp16 k_full [B,G,S,HD]
__device__ __half g_vh   [Bb*Gg*HD*SS];  // fp16 v_full transposed [B,G,HD,S], keys permuted in 16-groups
__device__ unsigned long long g_mb[Bb*Tt*64]; // mask bitmask: [b*T + t][tile]

// Side-stream resources, created once at program load (before any capture).
struct GpuRes {
    cudaStream_t s2;
    cudaEvent_t e0, e1, e2;
    GpuRes() {
        cudaStreamCreateWithFlags(&s2, cudaStreamNonBlocking);
        cudaEventCreateWithFlags(&e0, cudaEventDisableTiming);
        cudaEventCreateWithFlags(&e1, cudaEventDisableTiming);
        cudaEventCreateWithFlags(&e2, cudaEventDisableTiming);
    }
};
static GpuRes g_res;

// pack two floats into half2 (lo, hi)
__device__ __forceinline__ unsigned ph2(float lo, float hi) {
    unsigned r;
    asm("cvt.rn.f16x2.f32 %0, %1, %2;" : "=r"(r) : "f"(hi), "f"(lo));
    return r;
}

__device__ __forceinline__ void mma16(float* c,
    unsigned a0, unsigned a1, unsigned a2, unsigned a3,
    unsigned b0, unsigned b1)
{
    asm volatile(
        "mma.sync.aligned.m16n8k16.row.col.f32.f16.f16.f32 "
        "{%0,%1,%2,%3}, {%4,%5,%6,%7}, {%8,%9}, {%0,%1,%2,%3};"
        : "+f"(c[0]), "+f"(c[1]), "+f"(c[2]), "+f"(c[3])
        : "r"(a0), "r"(a1), "r"(a2), "r"(a3), "r"(b0), "r"(b1));
}

#define CPASYNC16(dst_sm, src_gm) \
    asm volatile("cp.async.cg.shared.global [%0], [%1], 16;\n" \
                 :: "r"(dst_sm), "l"(src_gm))

// key permutation within a 16-group so PV B-fragments are contiguous uint2
__device__ __forceinline__ int perm16(int s) {
    return ((s >> 1) & 3) * 4 + ((s >> 3) & 1) * 2 + (s & 1);
}

// ---------------------------------------------------------------------------
// Prep kernels
// ---------------------------------------------------------------------------
__global__ __launch_bounds__(256) void conv_x_kernel(
    const float4* __restrict__ src, uint2* __restrict__ dst, int n4)
{
    int i = blockIdx.x * blockDim.x + threadIdx.x;
    if (i >= n4) return;
    float4 v = src[i];
    dst[i] = make_uint2(ph2(v.x, v.y), ph2(v.z, v.w));
}

// Pack mask bytes into per-tile u64 bitmasks: out[row][tile], row = b*T+t.
__global__ __launch_bounds__(256) void pack_mask_kernel(
    const uint8_t* __restrict__ mask, unsigned long long* __restrict__ out)
{
    int i = blockIdx.x * blockDim.x + threadIdx.x;
    if (i >= Bb * Tt * 64) return;
    int tile = i & 63, row = i >> 6;
    const unsigned long long* src = (const unsigned long long*)
        (mask + (size_t)row * SS + tile * 64);
    unsigned long long bits = 0;
    #pragma unroll
    for (int c = 0; c < 8; c++) {
        unsigned long long w = src[c];
        #pragma unroll
        for (int j = 0; j < 8; j++)
            if ((w >> (8 * j)) & 0xFFull)
                bits |= 1ull << (c * 8 + j);
    }
    out[i] = bits;
}

// Transposed qkv weight pack (vectorized): dst[n][k] = fp16(w[k][n]).
__global__ __launch_bounds__(256) void pack_wqkvT_kernel(
    const float* __restrict__ qw, const float* __restrict__ kw,
    const float* __restrict__ vw, __half* __restrict__ dst)
{
    __shared__ float tile[64][65];
    int k0 = blockIdx.x << 6;
    int n0 = blockIdx.y << 6;
    const float* src; int ncol, nbase;
    if (n0 < 2048)      { src = qw; ncol = 2048; nbase = 0; }
    else if (n0 < 2560) { src = kw; ncol = 512;  nbase = 2048; }
    else                { src = vw; ncol = 512;  nbase = 2560; }

    #pragma unroll
    for (int t = 0; t < 4; t++) {
        int idx = threadIdx.x + (t << 8);
        int r = idx >> 4, c4 = (idx & 15) << 2;
        float4 v = *(const float4*)&src[(size_t)(k0 + r) * ncol + (n0 - nbase) + c4];
        tile[r][c4] = v.x; tile[r][c4 + 1] = v.y;
        tile[r][c4 + 2] = v.z; tile[r][c4 + 3] = v.w;
    }
    __syncthreads();
    #pragma unroll
    for (int t = 0; t < 2; t++) {
        int idx = threadIdx.x + (t << 8);
        int n = idx >> 3, c8 = idx & 7;
        __half h[8];
        #pragma unroll
        for (int j = 0; j < 8; j++)
            h[j] = __float2half_rn(tile[c8 * 8 + j][n]);
        *(uint4*)&dst[(size_t)(n0 + n) * 2048 + k0 + c8 * 8] = *(uint4*)h;
    }
}

// o_w transpose: dst[n][k] = fp16(src[k][n]), 2048x2048 (side stream, hidden)
__global__ __launch_bounds__(256) void transpose_ow_kernel(
    const float* __restrict__ src, __half* __restrict__ dst)
{
    __shared__ float tile[32][33];
    int k0 = blockIdx.x << 5, n0 = blockIdx.y << 5;
    int tx = threadIdx.x & 31, ty = threadIdx.x >> 5;
    #pragma unroll
    for (int r = 0; r < 32; r += 8)
        tile[ty + r][tx] = src[(size_t)(k0 + ty + r) * 2048 + n0 + tx];
    __syncthreads();
    #pragma unroll
    for (int r = 0; r < 32; r += 8)
        dst[(size_t)(n0 + ty + r) * 2048 + k0 + tx] =
            __float2half_rn(tile[tx][ty + r]);
}

// V cache portion: transpose + fp16 + key permutation, reads cache_v only.
// grid: (CACHEN/32, HD/32, B*G)  -- runs on the SIDE stream (no qkv dep).
__global__ __launch_bounds__(256) void transpose_v_cache_kernel(
    const float* __restrict__ cache_v, __half* __restrict__ dst)
{
    __shared__ float tile[32][33];
    int bg = blockIdx.z;
    int s0 = blockIdx.x << 5, d0 = blockIdx.y << 5;
    int tx = threadIdx.x & 31, ty = threadIdx.x >> 5;

    const float* s = cache_v + (size_t)bg * CACHEN * HD;
    #pragma unroll
    for (int r = 0; r < 32; r += 8)
        tile[ty + r][tx] = s[(size_t)(s0 + ty + r) * HD + d0 + tx];
    __syncthreads();
    __half* d = dst + (size_t)bg * HD * SS;
    int sp = s0 + (tx & ~15) + perm16(tx & 15);
    #pragma unroll
    for (int r = 0; r < 32; r += 8)
        d[(size_t)(d0 + ty + r) * SS + sp] = __float2half_rn(tile[tx][ty + r]);
}

// V new-token portion: reads qkv; writes fp16 transposed+permuted scratch AND
// the exact fp32 v_full output region (fuses the old scatter_v kernel).
// grid: (Tt/32, HD/32, B*G)  -- main stream, after the QKV GEMM.
__global__ __launch_bounds__(256) void transpose_v_new_kernel(
    const float* __restrict__ qkv, __half* __restrict__ dst,
    float* __restrict__ vf)
{
    __shared__ float tile[32][33];
    int bg = blockIdx.z;
    int b = bg >> 2, g = bg & 3;
    int t0 = blockIdx.x << 5, d0 = blockIdx.y << 5;
    int tx = threadIdx.x & 31, ty = threadIdx.x >> 5;

    #pragma unroll
    for (int r = 0; r < 32; r += 8) {
        int t = t0 + ty + r;
        float v = qkv[(size_t)(b * Tt + t) * 3072 + 2560 + g * HD + d0 + tx];
        tile[ty + r][tx] = v;
        vf[(((size_t)bg) * SS + CACHEN + t) * HD + d0 + tx] = v;  // exact fp32 out
    }
    __syncthreads();
    __half* d = dst + (size_t)bg * HD * SS;
    int s0 = CACHEN + t0;
    int sp = s0 + (tx & ~15) + perm16(tx & 15);
    #pragma unroll
    for (int r = 0; r < 32; r += 8)
        d[(size_t)(d0 + ty + r) * SS + sp] = __float2half_rn(tile[tx][ty + r]);
}

// ---------------------------------------------------------------------------
// fp16 GEMM (unchanged).
// ---------------------------------------------------------------------------
__global__ __launch_bounds__(256, 2) void gemm_h(
    const __half* __restrict__ A, const __half* __restrict__ Bm,
    float* __restrict__ C, int M, int N, int K)
{
    extern __shared__ unsigned sm[];
    unsigned* As = sm;
    unsigned* Bs = sm + 2 * 128 * 40;
    const int STG = 128 * 40;

    int tid = threadIdx.x, lane = tid & 31, warp = tid >> 5;
    int g = lane >> 2, tg = lane & 3;
    int m0 = blockIdx.y << 7, n0 = blockIdx.x << 7;
    int wm = (warp >> 2) << 6, wn = (warp & 3) << 5;

    float acc[4][4][4];
    #pragma unroll
    for (int i = 0; i < 4; i++)
        #pragma unroll
        for (int j = 0; j < 4; j++)
            #pragma unroll
            for (int e = 0; e < 4; e++) acc[i][j][e] = 0.0f;

    auto load_stage = [&](int it) {
        int s = it & 1;
        int k0 = it << 6;
        #pragma unroll
        for (int t = 0; t < 4; t++) {
            int c = tid + (t << 8);
            int row = c >> 3, ch = c & 7;
            unsigned da = (unsigned)__cvta_generic_to_shared(
                &As[s * STG + row * 40 + ch * 4]);
            CPASYNC16(da, A + (size_t)(m0 + row) * K + k0 + ch * 8);
            unsigned db = (unsigned)__cvta_generic_to_shared(
                &Bs[s * STG + row * 40 + ch * 4]);
            CPASYNC16(db, Bm + (size_t)(n0 + row) * K + k0 + ch * 8);
        }
        asm volatile("cp.async.commit_group;\n");
    };

    int niter = K >> 6;
    load_stage(0);

    for (int it = 0; it < niter; it++) {
        if (it + 1 < niter) {
            load_stage(it + 1);
            asm volatile("cp.async.wait_group 1;\n");
        } else {
            asm volatile("cp.async.wait_group 0;\n");
        }
        __syncthreads();

        const unsigned* Ab = As + (it & 1) * STG;
        const unsigned* Bbuf = Bs + (it & 1) * STG;
        #pragma unroll
        for (int ks = 0; ks < 4; ks++) {
            uint2 alo[4], ahi[4];
            #pragma unroll
            for (int mt = 0; mt < 4; mt++) {
                int r = wm + mt * 16;
                alo[mt] = *(const uint2*)&Ab[(r + g) * 40 + ks * 8 + 2 * tg];
                ahi[mt] = *(const uint2*)&Ab[(r + g + 8) * 40 + ks * 8 + 2 * tg];
            }
            #pragma unroll
            for (int nt = 0; nt < 4; nt++) {
                uint2 bb = *(const uint2*)&Bbuf[(wn + nt * 8 + g) * 40 + ks * 8 + 2 * tg];
                #pragma unroll
                for (int mt = 0; mt < 4; mt++)
                    mma16(acc[mt][nt], alo[mt].x, ahi[mt].x, alo[mt].y, ahi[mt].y,
                          bb.x, bb.y);
            }
        }
        __syncthreads();
    }

    #pragma unroll
    for (int mt = 0; mt < 4; mt++)
        #pragma unroll
        for (int nt = 0; nt < 4; nt++) {
            int r0 = m0 + wm + mt * 16 + g;
            int c  = n0 + wn + nt * 8 + 2 * tg;
            float2 v0 = make_float2(acc[mt][nt][0], acc[mt][nt][1]);
            float2 v1 = make_float2(acc[mt][nt][2], acc[mt][nt][3]);
            *(float2*)&C[(size_t)r0 * N + c] = v0;
            *(float2*)&C[(size_t)(r0 + 8) * N + c] = v1;
        }
}

// ---------------------------------------------------------------------------
// Fused per-head RMSNorm + RoPE; fp32 out (nullable) + fp16 out (nullable).
// ---------------------------------------------------------------------------
__global__ __launch_bounds__(128) void norm_rope_kernel(
    const float* __restrict__ raw, int coloff, const float* __restrict__ nw,
    const float* __restrict__ cosT, const float* __restrict__ sinT,
    const int* __restrict__ pos, float* __restrict__ outf,
    __half* __restrict__ outh, float hscale, int NH, int Tout, int toff)
{
    int idx = blockIdx.x;
    int h  = idx % NH;
    int bt = idx / NH;
    int t  = bt % Tt;
    int b  = bt / Tt;
    int d  = threadIdx.x;

    __shared__ float zn[128];
    __shared__ float red[4];

    float z = raw[(size_t)bt * 3072 + coloff + h * HD + d];
    float ss = z * z;
    #pragma unroll
    for (int o = 16; o; o >>= 1) ss += __shfl_xor_sync(0xffffffffu, ss, o);
    if ((d & 31) == 0) red[d >> 5] = ss;
    __syncthreads();
    float tot = red[0] + red[1] + red[2] + red[3];
    float r = rsqrtf(tot * (1.0f / 128.0f) + 1e-6f);
    float v = z * r * nw[d];
    zn[d] = v;
    __syncthreads();

    int p = pos[bt];
    float c = cosT[p * HD + d];
    float s = sinT[p * HD + d];
    float rot = (d < 64) ? -zn[d + 64] : zn[d - 64];
    float o = fmaf(v, c, rot * s);
    size_t oi = (((size_t)b * NH + h) * Tout + (toff + t)) * HD + d;
    if (outf) outf[oi] = o;
    if (outh) outh[oi] = __float2half_rn(o * hscale);
}

// Cache copy: exact fp32 + optional fp16
__global__ __launch_bounds__(256) void copy_cache_kernel(
    const float4* __restrict__ src, float4* __restrict__ dst,
    uint2* __restrict__ dsth)
{
    int i = blockIdx.x * blockDim.x + threadIdx.x;
    const int per = CACHEN * HD / 4;
    const int n4  = Bb * Gg * per;
    if (i >= n4) return;
    int bg = i / per, r = i % per;
    size_t oi = (size_t)bg * (SS * HD / 4) + r;
    float4 v = src[i];
    dst[oi] = v;
    if (dsth) dsth[oi] = make_uint2(ph2(v.x, v.y), ph2(v.z, v.w));
}

// ---------------------------------------------------------------------------
// fp16 flash attention (round-12 version: 8 warps, 2 CTAs/SM, bitmask mask).
// ---------------------------------------------------------------------------
__global__ __launch_bounds__(256, 2) void attn_h(
    const __half* __restrict__ qh, const __half* __restrict__ kh,
    const __half* __restrict__ vh, const unsigned long long* __restrict__ mbits,
    __half* __restrict__ ctxh)
{
    extern __shared__ unsigned sm[];
    unsigned* Qs = sm;                           // [128][72] words
    unsigned* Ks = sm + 128 * 72;                // 2 x [64][72]
    unsigned* Vs = sm + 128 * 72 + 2 * 64 * 72;  // 2 x [128][40]
    const int KSTG = 64 * 72, VSTG = 128 * 40;

    int qt = blockIdx.x, h = blockIdx.y, b = blockIdx.z;
    int gh = h >> 2;
    int tid = threadIdx.x, lane = tid & 31, wq = tid >> 5;
    int g = lane >> 2, tg = lane & 3;

    const __half* kb = kh + ((size_t)b * Gg + gh) * SS * HD;
    const __half* vb = vh + ((size_t)b * Gg + gh) * (size_t)HD * SS;
    const unsigned long long* mb = mbits + ((size_t)b * Tt + qt * 128) * 64;

    {
        const __half* qbase = qh + (((size_t)b * Hh + h) * Tt + qt * 128) * HD;
        #pragma unroll
        for (int t = 0; t < 8; t++) {
            int c = tid + (t << 8);
            int row = c >> 4, ch = c & 15;
            unsigned dq = (unsigned)__cvta_generic_to_shared(
                &Qs[row * 72 + ch * 4]);
            CPASYNC16(dq, qbase + (size_t)row * HD + ch * 8);
        }
    }

    auto load_stage = [&](int ti, int s) {
        #pragma unroll
        for (int t = 0; t < 4; t++) {
            int c = tid + (t << 8);
            int krow = c >> 4, kch = c & 15;
            unsigned dk = (unsigned)__cvta_generic_to_shared(
                &Ks[s * KSTG + krow * 72 + kch * 4]);
            CPASYNC16(dk, kb + (size_t)(ti * 64 + krow) * HD + kch * 8);
            int vrow = c >> 3, vch = c & 7;
            unsigned dv = (unsigned)__cvta_generic_to_shared(
                &Vs[s * VSTG + vrow * 40 + vch * 4]);
            CPASYNC16(dv, vb + (size_t)vrow * SS + ti * 64 + vch * 8);
        }
        asm volatile("cp.async.commit_group;\n");
    };

    float oacc[16][4];
    #pragma unroll
    for (int nt = 0; nt < 16; nt++)
        #pragma unroll
        for (int e = 0; e < 4; e++) oacc[nt][e] = 0.0f;
    float m0r = -1e30f, m1r = -1e30f, l0 = 0.0f, l1 = 0.0f;
    int qrow = wq * 16;

    load_stage(0, 0);

    const int NT = SS / 64;
    for (int ti = 0; ti < NT; ti++) {
        unsigned long long mb0 = mb[(size_t)(qrow + g) * 64 + ti];
        unsigned long long mb1 = mb[(size_t)(qrow + g + 8) * 64 + ti];

        if (ti + 1 < NT) {
            load_stage(ti + 1, (ti + 1) & 1);
            asm volatile("cp.async.wait_group 1;\n");
        } else {
            asm volatile("cp.async.wait_group 0;\n");
        }
        __syncthreads();

        const unsigned* Kb = Ks + (ti & 1) * KSTG;
        const unsigned* Vb = Vs + (ti & 1) * VSTG;

        float sacc[8][4];
        #pragma unroll
        for (int nt = 0; nt < 8; nt++)
            #pragma unroll
            for (int e = 0; e < 4; e++) sacc[nt][e] = 0.0f;

        #pragma unroll
        for (int ks = 0; ks < 8; ks++) {
            uint2 qlo = *(const uint2*)&Qs[(qrow + g) * 72 + ks * 8 + 2 * tg];
            uint2 qhi = *(const uint2*)&Qs[(qrow + g + 8) * 72 + ks * 8 + 2 * tg];
            #pragma unroll
            for (int nt = 0; nt < 8; nt++) {
                uint2 kk = *(const uint2*)&Kb[(nt * 8 + g) * 72 + ks * 8 + 2 * tg];
                mma16(sacc[nt], qlo.x, qhi.x, qlo.y, qhi.y, kk.x, kk.y);
            }
        }

        #pragma unroll
        for (int nt = 0; nt < 8; nt++) {
            int sh = nt * 8 + 2 * tg;
            if ((mb0 >> sh) & 1)       sacc[nt][0] = -1e30f;
            if ((mb0 >> (sh + 1)) & 1) sacc[nt][1] = -1e30f;
            if ((mb1 >> sh) & 1)       sacc[nt][2] = -1e30f;
            if ((mb1 >> (sh + 1)) & 1) sacc[nt][3] = -1e30f;
        }

        float mx0 = -1e30f, mx1 = -1e30f;
        #pragma unroll
        for (int nt = 0; nt < 8; nt++) {
            mx0 = fmaxf(mx0, fmaxf(sacc[nt][0], sacc[nt][1]));
            mx1 = fmaxf(mx1, fmaxf(sacc[nt][2], sacc[nt][3]));
        }
        mx0 = fmaxf(mx0, __shfl_xor_sync(0xffffffffu, mx0, 1));
        mx0 = fmaxf(mx0, __shfl_xor_sync(0xffffffffu, mx0, 2));
        mx1 = fmaxf(mx1, __shfl_xor_sync(0xffffffffu, mx1, 1));
        mx1 = fmaxf(mx1, __shfl_xor_sync(0xffffffffu, mx1, 2));
        float mn0 = fmaxf(m0r, mx0), mn1 = fmaxf(m1r, mx1);
        float al0 = __expf(m0r - mn0), al1 = __expf(m1r - mn1);
        m0r = mn0; m1r = mn1;

        float p[8][4];
        float rs0 = 0.0f, rs1 = 0.0f;
        #pragma unroll
        for (int nt = 0; nt < 8; nt++) {
            p[nt][0] = __expf(sacc[nt][0] - mn0);
            p[nt][1] = __expf(sacc[nt][1] - mn0);
            p[nt][2] = __expf(sacc[nt][2] - mn1);
            p[nt][3] = __expf(sacc[nt][3] - mn1);
            rs0 += p[nt][0] + p[nt][1]; rs1 += p[nt][2] + p[nt][3];
        }
        rs0 += __shfl_xor_sync(0xffffffffu, rs0, 1);
        rs0 += __shfl_xor_sync(0xffffffffu, rs0, 2);
        rs1 += __shfl_xor_sync(0xffffffffu, rs1, 1);
        rs1 += __shfl_xor_sync(0xffffffffu, rs1, 2);
        l0 = l0 * al0 + rs0;
        l1 = l1 * al1 + rs1;

        #pragma unroll
        for (int nt = 0; nt < 16; nt++) {
            oacc[nt][0] *= al0; oacc[nt][1] *= al0;
            oacc[nt][2] *= al1; oacc[nt][3] *= al1;
        }

        #pragma unroll
        for (int w = 0; w < 4; w++) {
            unsigned a0 = ph2(p[2*w][0],   p[2*w][1]);
            unsigned a1 = ph2(p[2*w][2],   p[2*w][3]);
            unsigned a2 = ph2(p[2*w+1][0], p[2*w+1][1]);
            unsigned a3 = ph2(p[2*w+1][2], p[2*w+1][3]);
            #pragma unroll
            for (int nt = 0; nt < 16; nt++) {
                uint2 vv = *(const uint2*)&Vb[(nt * 8 + g) * 40 + w * 8 + 2 * tg];
                mma16(oacc[nt], a0, a1, a2, a3, vv.x, vv.y);
            }
        }
        __syncthreads();
    }

    float il0 = 1.0f / l0, il1 = 1.0f / l1;
    int tok0 = qt * 128 + qrow + g;
    #pragma unroll
    for (int nt = 0; nt < 16; nt++) {
        int d = nt * 8 + 2 * tg;
        unsigned w0 = ph2(oacc[nt][0] * il0, oacc[nt][1] * il0);
        unsigned w1 = ph2(oacc[nt][2] * il1, oacc[nt][3] * il1);
        *(unsigned*)&ctxh[(((size_t)b * Tt + tok0) * Hh + h) * HD + d] = w0;
        *(unsigned*)&ctxh[(((size_t)b * Tt + tok0 + 8) * Hh + h) * HD + d] = w1;
    }
}

// ---------------------------------------------------------------------------
extern "C" void kernel_launch(void* const* d_in, const int* in_sizes, int n_in,
                              void* d_out, int out_size)
{
    const float*   x       = (const float*)d_in[0];
    const uint8_t* mask    = (const uint8_t*)d_in[1];
    const float*   cosT    = (const float*)d_in[2];
    const float*   sinT    = (const float*)d_in[3];
    const int*     pos     = (const int*)d_in[4];
    const float*   cache_k = (const float*)d_in[5];
    const float*   cache_v = (const float*)d_in[6];
    const float*   q_w     = (const float*)d_in[7];
    const float*   k_w     = (const float*)d_in[8];
    const float*   v_w     = (const float*)d_in[9];
    const float*   o_w     = (const float*)d_in[10];
    const float*   qn_w    = (const float*)d_in[11];
    const float*   kn_w    = (const float*)d_in[12];

    float* out_ctx = (float*)d_out;
    float* out_k   = out_ctx + (size_t)Bb * Tt * Hh * HD;
    float* out_v   = out_k   + (size_t)Bb * Gg * SS * HD;

    __half *xh, *wqkvh, *owh, *qhp, *ctxh, *khp, *vhp;
    float *qkv;
    unsigned long long *mbp;
    cudaGetSymbolAddress((void**)&xh,    g_xh);
    cudaGetSymbolAddress((void**)&wqkvh, g_wqkvh);
    cudaGetSymbolAddress((void**)&owh,   g_owh);
    cudaGetSymbolAddress((void**)&qkv,   g_qkv);
    cudaGetSymbolAddress((void**)&qhp,   g_qh);
    cudaGetSymbolAddress((void**)&ctxh,  g_ctxh);
    cudaGetSymbolAddress((void**)&khp,   g_kh);
    cudaGetSymbolAddress((void**)&vhp,   g_vh);
    cudaGetSymbolAddress((void**)&mbp,   g_mb);

    // Fork side stream: weight pack FIRST (main waits on it before the GEMM),
    // then copy/convert work + V-cache transpose (all input-only deps).
    cudaEventRecord(g_res.e0, 0);
    cudaStreamWaitEvent(g_res.s2, g_res.e0, 0);
    pack_wqkvT_kernel<<<dim3(32, 48), 256, 0, g_res.s2>>>(q_w, k_w, v_w, wqkvh);
    cudaEventRecord(g_res.e1, g_res.s2);
    {
        int n4 = Bb * Gg * CACHEN * HD / 4;
        int blocks = (n4 + 255) / 256;
        copy_cache_kernel<<<blocks, 256, 0, g_res.s2>>>(
            (const float4*)cache_k, (float4*)out_k, (uint2*)khp);
        copy_cache_kernel<<<blocks, 256, 0, g_res.s2>>>(
            (const float4*)cache_v, (float4*)out_v, nullptr);
        transpose_ow_kernel<<<dim3(64, 64), 256, 0, g_res.s2>>>(o_w, owh);
        int nm = Bb * Tt * 64;
        pack_mask_kernel<<<(nm + 255) / 256, 256, 0, g_res.s2>>>(mask, mbp);
        transpose_v_cache_kernel<<<dim3(CACHEN / 32, HD / 32, Bb * Gg), 256, 0, g_res.s2>>>(
            cache_v, vhp);
    }
    cudaEventRecord(g_res.e2, g_res.s2);

    // Main stream: x conversion (concurrent with the weight pack on s2).
    {
        int n4x = 2048 * 2048 / 4;
        conv_x_kernel<<<(n4x + 255) / 256, 256>>>((const float4*)x, (uint2*)xh, n4x);
    }
    cudaStreamWaitEvent(0, g_res.e1, 0);

    // fused QKV projection: [2048,2048] @ [3072,2048]^T, fp16 mma
    size_t gsmem = (size_t)(4 * 128 * 40) * 4;
    cudaFuncSetAttribute(gemm_h, cudaFuncAttributeMaxDynamicSharedMemorySize, (int)gsmem);
    gemm_h<<<dim3(24, 16), 256, gsmem>>>(xh, wqkvh, qkv, 2048, 3072, 2048);

    // new-token V: transpose+permute to scratch, and exact fp32 into v_full
    transpose_v_new_kernel<<<dim3(Tt / 32, HD / 32, Bb * Gg), 256>>>(qkv, vhp, out_v);

    // RMSNorm + RoPE; Q -> fp16 scratch (pre-scaled); K -> fp32 out + fp16 scratch
    const float scale = 0.08838834764831845f;   // 1/sqrt(128)
    norm_rope_kernel<<<Bb * Tt * Hh, 128>>>(qkv, 0,    qn_w, cosT, sinT, pos,
                                            nullptr, qhp, scale, Hh, Tt, 0);
    norm_rope_kernel<<<Bb * Tt * Gg, 128>>>(qkv, 2048, kn_w, cosT, sinT, pos,
                                            out_k, khp, 1.0f, Gg, SS, CACHEN);

    // Join: attention needs khp/vhp cache halves + mask bits; O-GEMM needs owh.
    cudaStreamWaitEvent(0, g_res.e2, 0);

    // attention (fp16 mma, 8 warps, 2 CTAs/SM, bitmask mask path)
    size_t smem = (size_t)(128 * 72 + 2 * 64 * 72 + 2 * 128 * 40) * 4;  // 114688
    cudaFuncSetAttribute(attn_h, cudaFuncAttributeMaxDynamicSharedMemorySize, (int)smem);
    attn_h<<<dim3(Tt / 128, Hh, Bb), 256, smem>>>(qhp, khp, vhp, mbp, ctxh);

    // output projection: [2048,2048] @ [2048,2048]^T, fp16 mma
    gemm_h<<<dim3(16, 16), 256, gsmem>>>(ctxh, owh, out_ctx, 2048, 2048, 2048);
}

// round 16
// speedup vs baseline: 1.0987x; 1.0090x over previous
#include <cuda_runtime.h>
#include <cuda_fp16.h>
#include <stdint.h>

#define Bb 4
#define Tt 512
#define Hh 16
#define Gg 4
#define HD 128
#define CACHEN 3584
#define SS 4096

// Scratch (static device arrays; no allocation allowed)
__device__ __half g_xh   [2048*2048];    // fp16 x               [M,K] K-major
__device__ __half g_wqkvh[3072*2048];    // fp16 qkv weights     [N,K] K-major
__device__ __half g_owh  [2048*2048];    // fp16 o_w             [N,K] K-major
__device__ float  g_qkv  [2048*3072];    // fused projection output (fp32)
__device__ __half g_qh   [Bb*Hh*Tt*HD];  // fp16 Q (pre-scaled) [B,H,T,HD]
__device__ __half g_ctxh [Bb*Tt*Hh*HD];  // fp16 ctx [B,T,H*HD]
__device__ __half g_kh   [Bb*Gg*SS*HD];  // fp16 k_full [B,G,S,HD]
__device__ __half g_vh   [Bb*Gg*HD*SS];  // fp16 v_full transposed [B,G,HD,S], keys permuted in 16-groups
__device__ unsigned long long g_mb[Bb*Tt*64]; // mask bitmask: [b*T + t][tile]

// Side-stream resources, created once at program load (before any capture).
struct GpuRes {
    cudaStream_t s2;
    cudaEvent_t e0, e1, e2;
    GpuRes() {
        cudaStreamCreateWithFlags(&s2, cudaStreamNonBlocking);
        cudaEventCreateWithFlags(&e0, cudaEventDisableTiming);
        cudaEventCreateWithFlags(&e1, cudaEventDisableTiming);
        cudaEventCreateWithFlags(&e2, cudaEventDisableTiming);
    }
};
static GpuRes g_res;

// pack two floats into half2 (lo, hi)
__device__ __forceinline__ unsigned ph2(float lo, float hi) {
    unsigned r;
    asm("cvt.rn.f16x2.f32 %0, %1, %2;" : "=r"(r) : "f"(hi), "f"(lo));
    return r;
}

__device__ __forceinline__ void mma16(float* c,
    unsigned a0, unsigned a1, unsigned a2, unsigned a3,
    unsigned b0, unsigned b1)
{
    asm volatile(
        "mma.sync.aligned.m16n8k16.row.col.f32.f16.f16.f32 "
        "{%0,%1,%2,%3}, {%4,%5,%6,%7}, {%8,%9}, {%0,%1,%2,%3};"
        : "+f"(c[0]), "+f"(c[1]), "+f"(c[2]), "+f"(c[3])
        : "r"(a0), "r"(a1), "r"(a2), "r"(a3), "r"(b0), "r"(b1));
}

#define CPASYNC16(dst_sm, src_gm) \
    asm volatile("cp.async.cg.shared.global [%0], [%1], 16;\n" \
                 :: "r"(dst_sm), "l"(src_gm))

// key permutation within a 16-group so PV B-fragments are contiguous uint2
__device__ __forceinline__ int perm16(int s) {
    return ((s >> 1) & 3) * 4 + ((s >> 3) & 1) * 2 + (s & 1);
}

// ---------------------------------------------------------------------------
// Prep kernels
// ---------------------------------------------------------------------------
__global__ __launch_bounds__(256) void conv_x_kernel(
    const float4* __restrict__ src, uint2* __restrict__ dst, int n4)
{
    int i = blockIdx.x * blockDim.x + threadIdx.x;
    if (i >= n4) return;
    float4 v = src[i];
    dst[i] = make_uint2(ph2(v.x, v.y), ph2(v.z, v.w));
}

// Pack mask bytes into per-tile u64 bitmasks: out[row][tile], row = b*T+t.
__global__ __launch_bounds__(256) void pack_mask_kernel(
    const uint8_t* __restrict__ mask, unsigned long long* __restrict__ out)
{
    int i = blockIdx.x * blockDim.x + threadIdx.x;
    if (i >= Bb * Tt * 64) return;
    int tile = i & 63, row = i >> 6;
    const unsigned long long* src = (const unsigned long long*)
        (mask + (size_t)row * SS + tile * 64);
    unsigned long long bits = 0;
    #pragma unroll
    for (int c = 0; c < 8; c++) {
        unsigned long long w = src[c];
        #pragma unroll
        for (int j = 0; j < 8; j++)
            if ((w >> (8 * j)) & 0xFFull)
                bits |= 1ull << (c * 8 + j);
    }
    out[i] = bits;
}

// Transposed qkv weight pack (vectorized): dst[n][k] = fp16(w[k][n]).
__global__ __launch_bounds__(256) void pack_wqkvT_kernel(
    const float* __restrict__ qw, const float* __restrict__ kw,
    const float* __restrict__ vw, __half* __restrict__ dst)
{
    __shared__ float tile[64][65];
    int k0 = blockIdx.x << 6;
    int n0 = blockIdx.y << 6;
    const float* src; int ncol, nbase;
    if (n0 < 2048)      { src = qw; ncol = 2048; nbase = 0; }
    else if (n0 < 2560) { src = kw; ncol = 512;  nbase = 2048; }
    else                { src = vw; ncol = 512;  nbase = 2560; }

    #pragma unroll
    for (int t = 0; t < 4; t++) {
        int idx = threadIdx.x + (t << 8);
        int r = idx >> 4, c4 = (idx & 15) << 2;
        float4 v = *(const float4*)&src[(size_t)(k0 + r) * ncol + (n0 - nbase) + c4];
        tile[r][c4] = v.x; tile[r][c4 + 1] = v.y;
        tile[r][c4 + 2] = v.z; tile[r][c4 + 3] = v.w;
    }
    __syncthreads();
    #pragma unroll
    for (int t = 0; t < 2; t++) {
        int idx = threadIdx.x + (t << 8);
        int n = idx >> 3, c8 = idx & 7;
        __half h[8];
        #pragma unroll
        for (int j = 0; j < 8; j++)
            h[j] = __float2half_rn(tile[c8 * 8 + j][n]);
        *(uint4*)&dst[(size_t)(n0 + n) * 2048 + k0 + c8 * 8] = *(uint4*)h;
    }
}

// o_w transpose: dst[n][k] = fp16(src[k][n]), 2048x2048 (side stream, hidden)
__global__ __launch_bounds__(256) void transpose_ow_kernel(
    const float* __restrict__ src, __half* __restrict__ dst)
{
    __shared__ float tile[32][33];
    int k0 = blockIdx.x << 5, n0 = blockIdx.y << 5;
    int tx = threadIdx.x & 31, ty = threadIdx.x >> 5;
    #pragma unroll
    for (int r = 0; r < 32; r += 8)
        tile[ty + r][tx] = src[(size_t)(k0 + ty + r) * 2048 + n0 + tx];
    __syncthreads();
    #pragma unroll
    for (int r = 0; r < 32; r += 8)
        dst[(size_t)(n0 + ty + r) * 2048 + k0 + tx] =
            __float2half_rn(tile[tx][ty + r]);
}

// V cache portion: transpose + fp16 + key permutation, reads cache_v only.
__global__ __launch_bounds__(256) void transpose_v_cache_kernel(
    const float* __restrict__ cache_v, __half* __restrict__ dst)
{
    __shared__ float tile[32][33];
    int bg = blockIdx.z;
    int s0 = blockIdx.x << 5, d0 = blockIdx.y << 5;
    int tx = threadIdx.x & 31, ty = threadIdx.x >> 5;

    const float* s = cache_v + (size_t)bg * CACHEN * HD;
    #pragma unroll
    for (int r = 0; r < 32; r += 8)
        tile[ty + r][tx] = s[(size_t)(s0 + ty + r) * HD + d0 + tx];
    __syncthreads();
    __half* d = dst + (size_t)bg * HD * SS;
    int sp = s0 + (tx & ~15) + perm16(tx & 15);
    #pragma unroll
    for (int r = 0; r < 32; r += 8)
        d[(size_t)(d0 + ty + r) * SS + sp] = __float2half_rn(tile[tx][ty + r]);
}

// V new-token portion: reads qkv; writes fp16 transposed+permuted scratch AND
// the exact fp32 v_full output region (fused scatter).
__global__ __launch_bounds__(256) void transpose_v_new_kernel(
    const float* __restrict__ qkv, __half* __restrict__ dst,
    float* __restrict__ vf)
{
    __shared__ float tile[32][33];
    int bg = blockIdx.z;
    int b = bg >> 2, g = bg & 3;
    int t0 = blockIdx.x << 5, d0 = blockIdx.y << 5;
    int tx = threadIdx.x & 31, ty = threadIdx.x >> 5;

    #pragma unroll
    for (int r = 0; r < 32; r += 8) {
        int t = t0 + ty + r;
        float v = qkv[(size_t)(b * Tt + t) * 3072 + 2560 + g * HD + d0 + tx];
        tile[ty + r][tx] = v;
        vf[(((size_t)bg) * SS + CACHEN + t) * HD + d0 + tx] = v;  // exact fp32 out
    }
    __syncthreads();
    __half* d = dst + (size_t)bg * HD * SS;
    int s0 = CACHEN + t0;
    int sp = s0 + (tx & ~15) + perm16(tx & 15);
    #pragma unroll
    for (int r = 0; r < 32; r += 8)
        d[(size_t)(d0 + ty + r) * SS + sp] = __float2half_rn(tile[tx][ty + r]);
}

// ---------------------------------------------------------------------------
// fp16 GEMM (unchanged).
// ---------------------------------------------------------------------------
__global__ __launch_bounds__(256, 2) void gemm_h(
    const __half* __restrict__ A, const __half* __restrict__ Bm,
    float* __restrict__ C, int M, int N, int K)
{
    extern __shared__ unsigned sm[];
    unsigned* As = sm;
    unsigned* Bs = sm + 2 * 128 * 40;
    const int STG = 128 * 40;

    int tid = threadIdx.x, lane = tid & 31, warp = tid >> 5;
    int g = lane >> 2, tg = lane & 3;
    int m0 = blockIdx.y << 7, n0 = blockIdx.x << 7;
    int wm = (warp >> 2) << 6, wn = (warp & 3) << 5;

    float acc[4][4][4];
    #pragma unroll
    for (int i = 0; i < 4; i++)
        #pragma unroll
        for (int j = 0; j < 4; j++)
            #pragma unroll
            for (int e = 0; e < 4; e++) acc[i][j][e] = 0.0f;

    auto load_stage = [&](int it) {
        int s = it & 1;
        int k0 = it << 6;
        #pragma unroll
        for (int t = 0; t < 4; t++) {
            int c = tid + (t << 8);
            int row = c >> 3, ch = c & 7;
            unsigned da = (unsigned)__cvta_generic_to_shared(
                &As[s * STG + row * 40 + ch * 4]);
            CPASYNC16(da, A + (size_t)(m0 + row) * K + k0 + ch * 8);
            unsigned db = (unsigned)__cvta_generic_to_shared(
                &Bs[s * STG + row * 40 + ch * 4]);
            CPASYNC16(db, Bm + (size_t)(n0 + row) * K + k0 + ch * 8);
        }
        asm volatile("cp.async.commit_group;\n");
    };

    int niter = K >> 6;
    load_stage(0);

    for (int it = 0; it < niter; it++) {
        if (it + 1 < niter) {
            load_stage(it + 1);
            asm volatile("cp.async.wait_group 1;\n");
        } else {
            asm volatile("cp.async.wait_group 0;\n");
        }
        __syncthreads();

        const unsigned* Ab = As + (it & 1) * STG;
        const unsigned* Bbuf = Bs + (it & 1) * STG;
        #pragma unroll
        for (int ks = 0; ks < 4; ks++) {
            uint2 alo[4], ahi[4];
            #pragma unroll
            for (int mt = 0; mt < 4; mt++) {
                int r = wm + mt * 16;
                alo[mt] = *(const uint2*)&Ab[(r + g) * 40 + ks * 8 + 2 * tg];
                ahi[mt] = *(const uint2*)&Ab[(r + g + 8) * 40 + ks * 8 + 2 * tg];
            }
            #pragma unroll
            for (int nt = 0; nt < 4; nt++) {
                uint2 bb = *(const uint2*)&Bbuf[(wn + nt * 8 + g) * 40 + ks * 8 + 2 * tg];
                #pragma unroll
                for (int mt = 0; mt < 4; mt++)
                    mma16(acc[mt][nt], alo[mt].x, ahi[mt].x, alo[mt].y, ahi[mt].y,
                          bb.x, bb.y);
            }
        }
        __syncthreads();
    }

    #pragma unroll
    for (int mt = 0; mt < 4; mt++)
        #pragma unroll
        for (int nt = 0; nt < 4; nt++) {
            int r0 = m0 + wm + mt * 16 + g;
            int c  = n0 + wn + nt * 8 + 2 * tg;
            float2 v0 = make_float2(acc[mt][nt][0], acc[mt][nt][1]);
            float2 v1 = make_float2(acc[mt][nt][2], acc[mt][nt][3]);
            *(float2*)&C[(size_t)r0 * N + c] = v0;
            *(float2*)&C[(size_t)(r0 + 8) * N + c] = v1;
        }
}

// ---------------------------------------------------------------------------
// Fused per-head RMSNorm + RoPE for Q AND K in ONE launch.
// Blocks [0, B*T*H): Q rows -> fp16 qh (pre-scaled).
// Blocks [B*T*H, B*T*(H+G)): K rows -> fp32 out_k + fp16 kh.
// ---------------------------------------------------------------------------
__global__ __launch_bounds__(128) void norm_rope_qk_kernel(
    const float* __restrict__ raw, const float* __restrict__ qnw,
    const float* __restrict__ knw, const float* __restrict__ cosT,
    const float* __restrict__ sinT, const int* __restrict__ pos,
    __half* __restrict__ qh, float* __restrict__ kf,
    __half* __restrict__ kh, float qscale)
{
    const int NQ = Bb * Tt * Hh;
    int idx = blockIdx.x;
    bool isQ = idx < NQ;
    int NH   = isQ ? Hh : Gg;
    int lidx = isQ ? idx : idx - NQ;
    int coloff = isQ ? 0 : 2048;
    const float* nw = isQ ? qnw : knw;

    int h  = lidx % NH;
    int bt = lidx / NH;
    int t  = bt % Tt;
    int b  = bt / Tt;
    int d  = threadIdx.x;

    __shared__ float zn[128];
    __shared__ float red[4];

    float z = raw[(size_t)bt * 3072 + coloff + h * HD + d];
    float ss = z * z;
    #pragma unroll
    for (int o = 16; o; o >>= 1) ss += __shfl_xor_sync(0xffffffffu, ss, o);
    if ((d & 31) == 0) red[d >> 5] = ss;
    __syncthreads();
    float tot = red[0] + red[1] + red[2] + red[3];
    float r = rsqrtf(tot * (1.0f / 128.0f) + 1e-6f);
    float v = z * r * nw[d];
    zn[d] = v;
    __syncthreads();

    int p = pos[bt];
    float c = cosT[p * HD + d];
    float s = sinT[p * HD + d];
    float rot = (d < 64) ? -zn[d + 64] : zn[d - 64];
    float o = fmaf(v, c, rot * s);

    if (isQ) {
        size_t oi = (((size_t)b * Hh + h) * Tt + t) * HD + d;
        qh[oi] = __float2half_rn(o * qscale);
    } else {
        size_t oi = (((size_t)b * Gg + h) * SS + CACHEN + t) * HD + d;
        kf[oi] = o;
        kh[oi] = __float2half_rn(o);
    }
}

// Cache copy: exact fp32 + optional fp16
__global__ __launch_bounds__(256) void copy_cache_kernel(
    const float4* __restrict__ src, float4* __restrict__ dst,
    uint2* __restrict__ dsth)
{
    int i = blockIdx.x * blockDim.x + threadIdx.x;
    const int per = CACHEN * HD / 4;
    const int n4  = Bb * Gg * per;
    if (i >= n4) return;
    int bg = i / per, r = i % per;
    size_t oi = (size_t)bg * (SS * HD / 4) + r;
    float4 v = src[i];
    dst[oi] = v;
    if (dsth) dsth[oi] = make_uint2(ph2(v.x, v.y), ph2(v.z, v.w));
}

// ---------------------------------------------------------------------------
// fp16 flash attention (round-12 version: 8 warps, 2 CTAs/SM, bitmask mask).
// ---------------------------------------------------------------------------
__global__ __launch_bounds__(256, 2) void attn_h(
    const __half* __restrict__ qh, const __half* __restrict__ kh,
    const __half* __restrict__ vh, const unsigned long long* __restrict__ mbits,
    __half* __restrict__ ctxh)
{
    extern __shared__ unsigned sm[];
    unsigned* Qs = sm;                           // [128][72] words
    unsigned* Ks = sm + 128 * 72;                // 2 x [64][72]
    unsigned* Vs = sm + 128 * 72 + 2 * 64 * 72;  // 2 x [128][40]
    const int KSTG = 64 * 72, VSTG = 128 * 40;

    int qt = blockIdx.x, h = blockIdx.y, b = blockIdx.z;
    int gh = h >> 2;
    int tid = threadIdx.x, lane = tid & 31, wq = tid >> 5;
    int g = lane >> 2, tg = lane & 3;

    const __half* kb = kh + ((size_t)b * Gg + gh) * SS * HD;
    const __half* vb = vh + ((size_t)b * Gg + gh) * (size_t)HD * SS;
    const unsigned long long* mb = mbits + ((size_t)b * Tt + qt * 128) * 64;

    {
        const __half* qbase = qh + (((size_t)b * Hh + h) * Tt + qt * 128) * HD;
        #pragma unroll
        for (int t = 0; t < 8; t++) {
            int c = tid + (t << 8);
            int row = c >> 4, ch = c & 15;
            unsigned dq = (unsigned)__cvta_generic_to_shared(
                &Qs[row * 72 + ch * 4]);
            CPASYNC16(dq, qbase + (size_t)row * HD + ch * 8);
        }
    }

    auto load_stage = [&](int ti, int s) {
        #pragma unroll
        for (int t = 0; t < 4; t++) {
            int c = tid + (t << 8);
            int krow = c >> 4, kch = c & 15;
            unsigned dk = (unsigned)__cvta_generic_to_shared(
                &Ks[s * KSTG + krow * 72 + kch * 4]);
            CPASYNC16(dk, kb + (size_t)(ti * 64 + krow) * HD + kch * 8);
            int vrow = c >> 3, vch = c & 7;
            unsigned dv = (unsigned)__cvta_generic_to_shared(
                &Vs[s * VSTG + vrow * 40 + vch * 4]);
            CPASYNC16(dv, vb + (size_t)vrow * SS + ti * 64 + vch * 8);
        }
        asm volatile("cp.async.commit_group;\n");
    };

    float oacc[16][4];
    #pragma unroll
    for (int nt = 0; nt < 16; nt++)
        #pragma unroll
        for (int e = 0; e < 4; e++) oacc[nt][e] = 0.0f;
    float m0r = -1e30f, m1r = -1e30f, l0 = 0.0f, l1 = 0.0f;
    int qrow = wq * 16;

    load_stage(0, 0);

    const int NT = SS / 64;
    for (int ti = 0; ti < NT; ti++) {
        unsigned long long mb0 = mb[(size_t)(qrow + g) * 64 + ti];
        unsigned long long mb1 = mb[(size_t)(qrow + g + 8) * 64 + ti];

        if (ti + 1 < NT) {
            load_stage(ti + 1, (ti + 1) & 1);
            asm volatile("cp.async.wait_group 1;\n");
        } else {
            asm volatile("cp.async.wait_group 0;\n");
        }
        __syncthreads();

        const unsigned* Kb = Ks + (ti & 1) * KSTG;
        const unsigned* Vb = Vs + (ti & 1) * VSTG;

        float sacc[8][4];
        #pragma unroll
        for (int nt = 0; nt < 8; nt++)
            #pragma unroll
            for (int e = 0; e < 4; e++) sacc[nt][e] = 0.0f;

        #pragma unroll
        for (int ks = 0; ks < 8; ks++) {
            uint2 qlo = *(const uint2*)&Qs[(qrow + g) * 72 + ks * 8 + 2 * tg];
            uint2 qhi = *(const uint2*)&Qs[(qrow + g + 8) * 72 + ks * 8 + 2 * tg];
            #pragma unroll
            for (int nt = 0; nt < 8; nt++) {
                uint2 kk = *(const uint2*)&Kb[(nt * 8 + g) * 72 + ks * 8 + 2 * tg];
                mma16(sacc[nt], qlo.x, qhi.x, qlo.y, qhi.y, kk.x, kk.y);
            }
        }

        #pragma unroll
        for (int nt = 0; nt < 8; nt++) {
            int sh = nt * 8 + 2 * tg;
            if ((mb0 >> sh) & 1)       sacc[nt][0] = -1e30f;
            if ((mb0 >> (sh + 1)) & 1) sacc[nt][1] = -1e30f;
            if ((mb1 >> sh) & 1)       sacc[nt][2] = -1e30f;
            if ((mb1 >> (sh + 1)) & 1) sacc[nt][3] = -1e30f;
        }

        float mx0 = -1e30f, mx1 = -1e30f;
        #pragma unroll
        for (int nt = 0; nt < 8; nt++) {
            mx0 = fmaxf(mx0, fmaxf(sacc[nt][0], sacc[nt][1]));
            mx1 = fmaxf(mx1, fmaxf(sacc[nt][2], sacc[nt][3]));
        }
        mx0 = fmaxf(mx0, __shfl_xor_sync(0xffffffffu, mx0, 1));
        mx0 = fmaxf(mx0, __shfl_xor_sync(0xffffffffu, mx0, 2));
        mx1 = fmaxf(mx1, __shfl_xor_sync(0xffffffffu, mx1, 1));
        mx1 = fmaxf(mx1, __shfl_xor_sync(0xffffffffu, mx1, 2));
        float mn0 = fmaxf(m0r, mx0), mn1 = fmaxf(m1r, mx1);
        float al0 = __expf(m0r - mn0), al1 = __expf(m1r - mn1);
        m0r = mn0; m1r = mn1;

        float p[8][4];
        float rs0 = 0.0f, rs1 = 0.0f;
        #pragma unroll
        for (int nt = 0; nt < 8; nt++) {
            p[nt][0] = __expf(sacc[nt][0] - mn0);
            p[nt][1] = __expf(sacc[nt][1] - mn0);
            p[nt][2] = __expf(sacc[nt][2] - mn1);
            p[nt][3] = __expf(sacc[nt][3] - mn1);
            rs0 += p[nt][0] + p[nt][1]; rs1 += p[nt][2] + p[nt][3];
        }
        rs0 += __shfl_xor_sync(0xffffffffu, rs0, 1);
        rs0 += __shfl_xor_sync(0xffffffffu, rs0, 2);
        rs1 += __shfl_xor_sync(0xffffffffu, rs1, 1);
        rs1 += __shfl_xor_sync(0xffffffffu, rs1, 2);
        l0 = l0 * al0 + rs0;
        l1 = l1 * al1 + rs1;

        #pragma unroll
        for (int nt = 0; nt < 16; nt++) {
            oacc[nt][0] *= al0; oacc[nt][1] *= al0;
            oacc[nt][2] *= al1; oacc[nt][3] *= al1;
        }

        #pragma unroll
        for (int w = 0; w < 4; w++) {
            unsigned a0 = ph2(p[2*w][0],   p[2*w][1]);
            unsigned a1 = ph2(p[2*w][2],   p[2*w][3]);
            unsigned a2 = ph2(p[2*w+1][0], p[2*w+1][1]);
            unsigned a3 = ph2(p[2*w+1][2], p[2*w+1][3]);
            #pragma unroll
            for (int nt = 0; nt < 16; nt++) {
                uint2 vv = *(const uint2*)&Vb[(nt * 8 + g) * 40 + w * 8 + 2 * tg];
                mma16(oacc[nt], a0, a1, a2, a3, vv.x, vv.y);
            }
        }
        __syncthreads();
    }

    float il0 = 1.0f / l0, il1 = 1.0f / l1;
    int tok0 = qt * 128 + qrow + g;
    #pragma unroll
    for (int nt = 0; nt < 16; nt++) {
        int d = nt * 8 + 2 * tg;
        unsigned w0 = ph2(oacc[nt][0] * il0, oacc[nt][1] * il0);
        unsigned w1 = ph2(oacc[nt][2] * il1, oacc[nt][3] * il1);
        *(unsigned*)&ctxh[(((size_t)b * Tt + tok0) * Hh + h) * HD + d] = w0;
        *(unsigned*)&ctxh[(((size_t)b * Tt + tok0 + 8) * Hh + h) * HD + d] = w1;
    }
}

// ---------------------------------------------------------------------------
extern "C" void kernel_launch(void* const* d_in, const int* in_sizes, int n_in,
                              void* d_out, int out_size)
{
    const float*   x       = (const float*)d_in[0];
    const uint8_t* mask    = (const uint8_t*)d_in[1];
    const float*   cosT    = (const float*)d_in[2];
    const float*   sinT    = (const float*)d_in[3];
    const int*     pos     = (const int*)d_in[4];
    const float*   cache_k = (const float*)d_in[5];
    const float*   cache_v = (const float*)d_in[6];
    const float*   q_w     = (const float*)d_in[7];
    const float*   k_w     = (const float*)d_in[8];
    const float*   v_w     = (const float*)d_in[9];
    const float*   o_w     = (const float*)d_in[10];
    const float*   qn_w    = (const float*)d_in[11];
    const float*   kn_w    = (const float*)d_in[12];

    float* out_ctx = (float*)d_out;
    float* out_k   = out_ctx + (size_t)Bb * Tt * Hh * HD;
    float* out_v   = out_k   + (size_t)Bb * Gg * SS * HD;

    __half *xh, *wqkvh, *owh, *qhp, *ctxh, *khp, *vhp;
    float *qkv;
    unsigned long long *mbp;
    cudaGetSymbolAddress((void**)&xh,    g_xh);
    cudaGetSymbolAddress((void**)&wqkvh, g_wqkvh);
    cudaGetSymbolAddress((void**)&owh,   g_owh);
    cudaGetSymbolAddress((void**)&qkv,   g_qkv);
    cudaGetSymbolAddress((void**)&qhp,   g_qh);
    cudaGetSymbolAddress((void**)&ctxh,  g_ctxh);
    cudaGetSymbolAddress((void**)&khp,   g_kh);
    cudaGetSymbolAddress((void**)&vhp,   g_vh);
    cudaGetSymbolAddress((void**)&mbp,   g_mb);

    // Fork side stream: weight pack FIRST (main waits on it before the GEMM),
    // then copy/convert work + V-cache transpose (all input-only deps).
    cudaEventRecord(g_res.e0, 0);
    cudaStreamWaitEvent(g_res.s2, g_res.e0, 0);
    pack_wqkvT_kernel<<<dim3(32, 48), 256, 0, g_res.s2>>>(q_w, k_w, v_w, wqkvh);
    cudaEventRecord(g_res.e1, g_res.s2);
    {
        int n4 = Bb * Gg * CACHEN * HD / 4;
        int blocks = (n4 + 255) / 256;
        copy_cache_kernel<<<blocks, 256, 0, g_res.s2>>>(
            (const float4*)cache_k, (float4*)out_k, (uint2*)khp);
        copy_cache_kernel<<<blocks, 256, 0, g_res.s2>>>(
            (const float4*)cache_v, (float4*)out_v, nullptr);
        transpose_ow_kernel<<<dim3(64, 64), 256, 0, g_res.s2>>>(o_w, owh);
        int nm = Bb * Tt * 64;
        pack_mask_kernel<<<(nm + 255) / 256, 256, 0, g_res.s2>>>(mask, mbp);
        transpose_v_cache_kernel<<<dim3(CACHEN / 32, HD / 32, Bb * Gg), 256, 0, g_res.s2>>>(
            cache_v, vhp);
    }
    cudaEventRecord(g_res.e2, g_res.s2);

    // Main stream: x conversion (concurrent with the weight pack on s2).
    {
        int n4x = 2048 * 2048 / 4;
        conv_x_kernel<<<(n4x + 255) / 256, 256>>>((const float4*)x, (uint2*)xh, n4x);
    }
    cudaStreamWaitEvent(0, g_res.e1, 0);

    // fused QKV projection: [2048,2048] @ [3072,2048]^T, fp16 mma
    size_t gsmem = (size_t)(4 * 128 * 40) * 4;
    cudaFuncSetAttribute(gemm_h, cudaFuncAttributeMaxDynamicSharedMemorySize, (int)gsmem);
    gemm_h<<<dim3(24, 16), 256, gsmem>>>(xh, wqkvh, qkv, 2048, 3072, 2048);

    // new-token V: transpose+permute to scratch, and exact fp32 into v_full
    transpose_v_new_kernel<<<dim3(Tt / 32, HD / 32, Bb * Gg), 256>>>(qkv, vhp, out_v);

    // Fused RMSNorm + RoPE for Q and K in one launch
    const float scale = 0.08838834764831845f;   // 1/sqrt(128)
    norm_rope_qk_kernel<<<Bb * Tt * (Hh + Gg), 128>>>(
        qkv, qn_w, kn_w, cosT, sinT, pos, qhp, out_k, khp, scale);

    // Join: attention needs khp/vhp cache halves + mask bits; O-GEMM needs owh.
    cudaStreamWaitEvent(0, g_res.e2, 0);

    // attention (fp16 mma, 8 warps, 2 CTAs/SM, bitmask mask path)
    size_t smem = (size_t)(128 * 72 + 2 * 64 * 72 + 2 * 128 * 40) * 4;  // 114688
    cudaFuncSetAttribute(attn_h, cudaFuncAttributeMaxDynamicSharedMemorySize, (int)smem);
    attn_h<<<dim3(Tt / 128, Hh, Bb), 256, smem>>>(qhp, khp, vhp, mbp, ctxh);

    // output projection: [2048,2048] @ [2048,2048]^T, fp16 mma
    gemm_h<<<dim3(16, 16), 256, gsmem>>>(ctxh, owh, out_ctx, 2048, 2048, 2048);
}

// round 17
// speedup vs baseline: 1.1430x; 1.0404x over previous
#include <cuda_runtime.h>
#include <cuda_fp16.h>
#include <stdint.h>

#define Bb 4
#define Tt 512
#define Hh 16
#define Gg 4
#define HD 128
#define CACHEN 3584
#define SS 4096

// Scratch (static device arrays; no allocation allowed)
__device__ __half g_xh   [2048*2048];    // fp16 x               [M,K] K-major
__device__ __half g_wqkvh[3072*2048];    // fp16 qkv weights     [N,K] K-major
__device__ __half g_owh  [2048*2048];    // fp16 o_w             [N,K] K-major
__device__ float  g_qkv  [2048*3072];    // fused projection output (fp32)
__device__ __half g_qh   [Bb*Hh*Tt*HD];  // fp16 Q (pre-scaled) [B,H,T,HD]
__device__ __half g_ctxh [Bb*Tt*Hh*HD];  // fp16 ctx [B,T,H*HD]
__device__ __half g_kh   [Bb*Gg*SS*HD];  // fp16 k_full [B,G,S,HD]
__device__ __half g_vh   [Bb*Gg*HD*SS];  // fp16 v_full transposed [B,G,HD,S], keys permuted in 16-groups
__device__ unsigned long long g_mb[Bb*Tt*64]; // mask bitmask: [b*T + t][tile]

// Side-stream resources, created once at program load (before any capture).
struct GpuRes {
    cudaStream_t s2;
    cudaEvent_t e0, e1, e2;
    GpuRes() {
        cudaStreamCreateWithFlags(&s2, cudaStreamNonBlocking);
        cudaEventCreateWithFlags(&e0, cudaEventDisableTiming);
        cudaEventCreateWithFlags(&e1, cudaEventDisableTiming);
        cudaEventCreateWithFlags(&e2, cudaEventDisableTiming);
    }
};
static GpuRes g_res;

// pack two floats into half2 (lo, hi)
__device__ __forceinline__ unsigned ph2(float lo, float hi) {
    unsigned r;
    asm("cvt.rn.f16x2.f32 %0, %1, %2;" : "=r"(r) : "f"(hi), "f"(lo));
    return r;
}

__device__ __forceinline__ void mma16(float* c,
    unsigned a0, unsigned a1, unsigned a2, unsigned a3,
    unsigned b0, unsigned b1)
{
    asm volatile(
        "mma.sync.aligned.m16n8k16.row.col.f32.f16.f16.f32 "
        "{%0,%1,%2,%3}, {%4,%5,%6,%7}, {%8,%9}, {%0,%1,%2,%3};"
        : "+f"(c[0]), "+f"(c[1]), "+f"(c[2]), "+f"(c[3])
        : "r"(a0), "r"(a1), "r"(a2), "r"(a3), "r"(b0), "r"(b1));
}

#define CPASYNC16(dst_sm, src_gm) \
    asm volatile("cp.async.cg.shared.global [%0], [%1], 16;\n" \
                 :: "r"(dst_sm), "l"(src_gm))

// key permutation within a 16-group so PV B-fragments are contiguous uint2
__device__ __forceinline__ int perm16(int s) {
    return ((s >> 1) & 3) * 4 + ((s >> 3) & 1) * 2 + (s & 1);
}

// ---------------------------------------------------------------------------
// Prep kernels
// ---------------------------------------------------------------------------
__global__ __launch_bounds__(256) void conv_x_kernel(
    const float4* __restrict__ src, uint2* __restrict__ dst, int n4)
{
    int i = blockIdx.x * blockDim.x + threadIdx.x;
    if (i >= n4) return;
    float4 v = src[i];
    dst[i] = make_uint2(ph2(v.x, v.y), ph2(v.z, v.w));
}

// Pack mask bytes into per-tile u64 bitmasks: out[row][tile], row = b*T+t.
__global__ __launch_bounds__(256) void pack_mask_kernel(
    const uint8_t* __restrict__ mask, unsigned long long* __restrict__ out)
{
    int i = blockIdx.x * blockDim.x + threadIdx.x;
    if (i >= Bb * Tt * 64) return;
    int tile = i & 63, row = i >> 6;
    const unsigned long long* src = (const unsigned long long*)
        (mask + (size_t)row * SS + tile * 64);
    unsigned long long bits = 0;
    #pragma unroll
    for (int c = 0; c < 8; c++) {
        unsigned long long w = src[c];
        #pragma unroll
        for (int j = 0; j < 8; j++)
            if ((w >> (8 * j)) & 0xFFull)
                bits |= 1ull << (c * 8 + j);
    }
    out[i] = bits;
}

// Transposed qkv weight pack (vectorized): dst[n][k] = fp16(w[k][n]).
__global__ __launch_bounds__(256) void pack_wqkvT_kernel(
    const float* __restrict__ qw, const float* __restrict__ kw,
    const float* __restrict__ vw, __half* __restrict__ dst)
{
    __shared__ float tile[64][65];
    int k0 = blockIdx.x << 6;
    int n0 = blockIdx.y << 6;
    const float* src; int ncol, nbase;
    if (n0 < 2048)      { src = qw; ncol = 2048; nbase = 0; }
    else if (n0 < 2560) { src = kw; ncol = 512;  nbase = 2048; }
    else                { src = vw; ncol = 512;  nbase = 2560; }

    #pragma unroll
    for (int t = 0; t < 4; t++) {
        int idx = threadIdx.x + (t << 8);
        int r = idx >> 4, c4 = (idx & 15) << 2;
        float4 v = *(const float4*)&src[(size_t)(k0 + r) * ncol + (n0 - nbase) + c4];
        tile[r][c4] = v.x; tile[r][c4 + 1] = v.y;
        tile[r][c4 + 2] = v.z; tile[r][c4 + 3] = v.w;
    }
    __syncthreads();
    #pragma unroll
    for (int t = 0; t < 2; t++) {
        int idx = threadIdx.x + (t << 8);
        int n = idx >> 3, c8 = idx & 7;
        __half h[8];
        #pragma unroll
        for (int j = 0; j < 8; j++)
            h[j] = __float2half_rn(tile[c8 * 8 + j][n]);
        *(uint4*)&dst[(size_t)(n0 + n) * 2048 + k0 + c8 * 8] = *(uint4*)h;
    }
}

// o_w transpose: dst[n][k] = fp16(src[k][n]), 2048x2048 (side stream, hidden)
__global__ __launch_bounds__(256) void transpose_ow_kernel(
    const float* __restrict__ src, __half* __restrict__ dst)
{
    __shared__ float tile[32][33];
    int k0 = blockIdx.x << 5, n0 = blockIdx.y << 5;
    int tx = threadIdx.x & 31, ty = threadIdx.x >> 5;
    #pragma unroll
    for (int r = 0; r < 32; r += 8)
        tile[ty + r][tx] = src[(size_t)(k0 + ty + r) * 2048 + n0 + tx];
    __syncthreads();
    #pragma unroll
    for (int r = 0; r < 32; r += 8)
        dst[(size_t)(n0 + ty + r) * 2048 + k0 + tx] =
            __float2half_rn(tile[tx][ty + r]);
}

// V cache portion: transpose + fp16 + key permutation, reads cache_v only.
__global__ __launch_bounds__(256) void transpose_v_cache_kernel(
    const float* __restrict__ cache_v, __half* __restrict__ dst)
{
    __shared__ float tile[32][33];
    int bg = blockIdx.z;
    int s0 = blockIdx.x << 5, d0 = blockIdx.y << 5;
    int tx = threadIdx.x & 31, ty = threadIdx.x >> 5;

    const float* s = cache_v + (size_t)bg * CACHEN * HD;
    #pragma unroll
    for (int r = 0; r < 32; r += 8)
        tile[ty + r][tx] = s[(size_t)(s0 + ty + r) * HD + d0 + tx];
    __syncthreads();
    __half* d = dst + (size_t)bg * HD * SS;
    int sp = s0 + (tx & ~15) + perm16(tx & 15);
    #pragma unroll
    for (int r = 0; r < 32; r += 8)
        d[(size_t)(d0 + ty + r) * SS + sp] = __float2half_rn(tile[tx][ty + r]);
}

// V new-token portion: reads qkv; writes fp16 transposed+permuted scratch AND
// the exact fp32 v_full output region (fused scatter).
__global__ __launch_bounds__(256) void transpose_v_new_kernel(
    const float* __restrict__ qkv, __half* __restrict__ dst,
    float* __restrict__ vf)
{
    __shared__ float tile[32][33];
    int bg = blockIdx.z;
    int b = bg >> 2, g = bg & 3;
    int t0 = blockIdx.x << 5, d0 = blockIdx.y << 5;
    int tx = threadIdx.x & 31, ty = threadIdx.x >> 5;

    #pragma unroll
    for (int r = 0; r < 32; r += 8) {
        int t = t0 + ty + r;
        float v = qkv[(size_t)(b * Tt + t) * 3072 + 2560 + g * HD + d0 + tx];
        tile[ty + r][tx] = v;
        vf[(((size_t)bg) * SS + CACHEN + t) * HD + d0 + tx] = v;  // exact fp32 out
    }
    __syncthreads();
    __half* d = dst + (size_t)bg * HD * SS;
    int s0 = CACHEN + t0;
    int sp = s0 + (tx & ~15) + perm16(tx & 15);
    #pragma unroll
    for (int r = 0; r < 32; r += 8)
        d[(size_t)(d0 + ty + r) * SS + sp] = __float2half_rn(tile[tx][ty + r]);
}

// ---------------------------------------------------------------------------
// fp16 GEMM (unchanged).
// ---------------------------------------------------------------------------
__global__ __launch_bounds__(256, 2) void gemm_h(
    const __half* __restrict__ A, const __half* __restrict__ Bm,
    float* __restrict__ C, int M, int N, int K)
{
    extern __shared__ unsigned sm[];
    unsigned* As = sm;
    unsigned* Bs = sm + 2 * 128 * 40;
    const int STG = 128 * 40;

    int tid = threadIdx.x, lane = tid & 31, warp = tid >> 5;
    int g = lane >> 2, tg = lane & 3;
    int m0 = blockIdx.y << 7, n0 = blockIdx.x << 7;
    int wm = (warp >> 2) << 6, wn = (warp & 3) << 5;

    float acc[4][4][4];
    #pragma unroll
    for (int i = 0; i < 4; i++)
        #pragma unroll
        for (int j = 0; j < 4; j++)
            #pragma unroll
            for (int e = 0; e < 4; e++) acc[i][j][e] = 0.0f;

    auto load_stage = [&](int it) {
        int s = it & 1;
        int k0 = it << 6;
        #pragma unroll
        for (int t = 0; t < 4; t++) {
            int c = tid + (t << 8);
            int row = c >> 3, ch = c & 7;
            unsigned da = (unsigned)__cvta_generic_to_shared(
                &As[s * STG + row * 40 + ch * 4]);
            CPASYNC16(da, A + (size_t)(m0 + row) * K + k0 + ch * 8);
            unsigned db = (unsigned)__cvta_generic_to_shared(
                &Bs[s * STG + row * 40 + ch * 4]);
            CPASYNC16(db, Bm + (size_t)(n0 + row) * K + k0 + ch * 8);
        }
        asm volatile("cp.async.commit_group;\n");
    };

    int niter = K >> 6;
    load_stage(0);

    for (int it = 0; it < niter; it++) {
        if (it + 1 < niter) {
            load_stage(it + 1);
            asm volatile("cp.async.wait_group 1;\n");
        } else {
            asm volatile("cp.async.wait_group 0;\n");
        }
        __syncthreads();

        const unsigned* Ab = As + (it & 1) * STG;
        const unsigned* Bbuf = Bs + (it & 1) * STG;
        #pragma unroll
        for (int ks = 0; ks < 4; ks++) {
            uint2 alo[4], ahi[4];
            #pragma unroll
            for (int mt = 0; mt < 4; mt++) {
                int r = wm + mt * 16;
                alo[mt] = *(const uint2*)&Ab[(r + g) * 40 + ks * 8 + 2 * tg];
                ahi[mt] = *(const uint2*)&Ab[(r + g + 8) * 40 + ks * 8 + 2 * tg];
            }
            #pragma unroll
            for (int nt = 0; nt < 4; nt++) {
                uint2 bb = *(const uint2*)&Bbuf[(wn + nt * 8 + g) * 40 + ks * 8 + 2 * tg];
                #pragma unroll
                for (int mt = 0; mt < 4; mt++)
                    mma16(acc[mt][nt], alo[mt].x, ahi[mt].x, alo[mt].y, ahi[mt].y,
                          bb.x, bb.y);
            }
        }
        __syncthreads();
    }

    #pragma unroll
    for (int mt = 0; mt < 4; mt++)
        #pragma unroll
        for (int nt = 0; nt < 4; nt++) {
            int r0 = m0 + wm + mt * 16 + g;
            int c  = n0 + wn + nt * 8 + 2 * tg;
            float2 v0 = make_float2(acc[mt][nt][0], acc[mt][nt][1]);
            float2 v1 = make_float2(acc[mt][nt][2], acc[mt][nt][3]);
            *(float2*)&C[(size_t)r0 * N + c] = v0;
            *(float2*)&C[(size_t)(r0 + 8) * N + c] = v1;
        }
}

// ---------------------------------------------------------------------------
// Fused per-head RMSNorm + RoPE for Q AND K in ONE launch.
// ---------------------------------------------------------------------------
__global__ __launch_bounds__(128) void norm_rope_qk_kernel(
    const float* __restrict__ raw, const float* __restrict__ qnw,
    const float* __restrict__ knw, const float* __restrict__ cosT,
    const float* __restrict__ sinT, const int* __restrict__ pos,
    __half* __restrict__ qh, float* __restrict__ kf,
    __half* __restrict__ kh, float qscale)
{
    const int NQ = Bb * Tt * Hh;
    int idx = blockIdx.x;
    bool isQ = idx < NQ;
    int NH   = isQ ? Hh : Gg;
    int lidx = isQ ? idx : idx - NQ;
    int coloff = isQ ? 0 : 2048;
    const float* nw = isQ ? qnw : knw;

    int h  = lidx % NH;
    int bt = lidx / NH;
    int t  = bt % Tt;
    int b  = bt / Tt;
    int d  = threadIdx.x;

    __shared__ float zn[128];
    __shared__ float red[4];

    float z = raw[(size_t)bt * 3072 + coloff + h * HD + d];
    float ss = z * z;
    #pragma unroll
    for (int o = 16; o; o >>= 1) ss += __shfl_xor_sync(0xffffffffu, ss, o);
    if ((d & 31) == 0) red[d >> 5] = ss;
    __syncthreads();
    float tot = red[0] + red[1] + red[2] + red[3];
    float r = rsqrtf(tot * (1.0f / 128.0f) + 1e-6f);
    float v = z * r * nw[d];
    zn[d] = v;
    __syncthreads();

    int p = pos[bt];
    float c = cosT[p * HD + d];
    float s = sinT[p * HD + d];
    float rot = (d < 64) ? -zn[d + 64] : zn[d - 64];
    float o = fmaf(v, c, rot * s);

    if (isQ) {
        size_t oi = (((size_t)b * Hh + h) * Tt + t) * HD + d;
        qh[oi] = __float2half_rn(o * qscale);
    } else {
        size_t oi = (((size_t)b * Gg + h) * SS + CACHEN + t) * HD + d;
        kf[oi] = o;
        kh[oi] = __float2half_rn(o);
    }
}

// Cache copy: exact fp32 + optional fp16
__global__ __launch_bounds__(256) void copy_cache_kernel(
    const float4* __restrict__ src, float4* __restrict__ dst,
    uint2* __restrict__ dsth)
{
    int i = blockIdx.x * blockDim.x + threadIdx.x;
    const int per = CACHEN * HD / 4;
    const int n4  = Bb * Gg * per;
    if (i >= n4) return;
    int bg = i / per, r = i % per;
    size_t oi = (size_t)bg * (SS * HD / 4) + r;
    float4 v = src[i];
    dst[oi] = v;
    if (dsth) dsth[oi] = make_uint2(ph2(v.x, v.y), ph2(v.z, v.w));
}

// ---------------------------------------------------------------------------
// fp16 flash attention. 8 warps, 2 CTAs/SM, bitmask mask; l-sum deferred to
// epilogue (per-lane partials, al is quad-uniform) and mask guarded.
// ---------------------------------------------------------------------------
__global__ __launch_bounds__(256, 2) void attn_h(
    const __half* __restrict__ qh, const __half* __restrict__ kh,
    const __half* __restrict__ vh, const unsigned long long* __restrict__ mbits,
    __half* __restrict__ ctxh)
{
    extern __shared__ unsigned sm[];
    unsigned* Qs = sm;                           // [128][72] words
    unsigned* Ks = sm + 128 * 72;                // 2 x [64][72]
    unsigned* Vs = sm + 128 * 72 + 2 * 64 * 72;  // 2 x [128][40]
    const int KSTG = 64 * 72, VSTG = 128 * 40;

    int qt = blockIdx.x, h = blockIdx.y, b = blockIdx.z;
    int gh = h >> 2;
    int tid = threadIdx.x, lane = tid & 31, wq = tid >> 5;
    int g = lane >> 2, tg = lane & 3;

    const __half* kb = kh + ((size_t)b * Gg + gh) * SS * HD;
    const __half* vb = vh + ((size_t)b * Gg + gh) * (size_t)HD * SS;
    const unsigned long long* mb = mbits + ((size_t)b * Tt + qt * 128) * 64;

    {
        const __half* qbase = qh + (((size_t)b * Hh + h) * Tt + qt * 128) * HD;
        #pragma unroll
        for (int t = 0; t < 8; t++) {
            int c = tid + (t << 8);
            int row = c >> 4, ch = c & 15;
            unsigned dq = (unsigned)__cvta_generic_to_shared(
                &Qs[row * 72 + ch * 4]);
            CPASYNC16(dq, qbase + (size_t)row * HD + ch * 8);
        }
    }

    auto load_stage = [&](int ti, int s) {
        #pragma unroll
        for (int t = 0; t < 4; t++) {
            int c = tid + (t << 8);
            int krow = c >> 4, kch = c & 15;
            unsigned dk = (unsigned)__cvta_generic_to_shared(
                &Ks[s * KSTG + krow * 72 + kch * 4]);
            CPASYNC16(dk, kb + (size_t)(ti * 64 + krow) * HD + kch * 8);
            int vrow = c >> 3, vch = c & 7;
            unsigned dv = (unsigned)__cvta_generic_to_shared(
                &Vs[s * VSTG + vrow * 40 + vch * 4]);
            CPASYNC16(dv, vb + (size_t)vrow * SS + ti * 64 + vch * 8);
        }
        asm volatile("cp.async.commit_group;\n");
    };

    float oacc[16][4];
    #pragma unroll
    for (int nt = 0; nt < 16; nt++)
        #pragma unroll
        for (int e = 0; e < 4; e++) oacc[nt][e] = 0.0f;
    float m0r = -1e30f, m1r = -1e30f;
    float l0 = 0.0f, l1 = 0.0f;   // per-lane partial row sums (quad-reduced at end)
    int qrow = wq * 16;

    load_stage(0, 0);

    const int NT = SS / 64;
    for (int ti = 0; ti < NT; ti++) {
        unsigned long long mb0 = mb[(size_t)(qrow + g) * 64 + ti];
        unsigned long long mb1 = mb[(size_t)(qrow + g + 8) * 64 + ti];

        if (ti + 1 < NT) {
            load_stage(ti + 1, (ti + 1) & 1);
            asm volatile("cp.async.wait_group 1;\n");
        } else {
            asm volatile("cp.async.wait_group 0;\n");
        }
        __syncthreads();

        const unsigned* Kb = Ks + (ti & 1) * KSTG;
        const unsigned* Vb = Vs + (ti & 1) * VSTG;

        float sacc[8][4];
        #pragma unroll
        for (int nt = 0; nt < 8; nt++)
            #pragma unroll
            for (int e = 0; e < 4; e++) sacc[nt][e] = 0.0f;

        #pragma unroll
        for (int ks = 0; ks < 8; ks++) {
            uint2 qlo = *(const uint2*)&Qs[(qrow + g) * 72 + ks * 8 + 2 * tg];
            uint2 qhi = *(const uint2*)&Qs[(qrow + g + 8) * 72 + ks * 8 + 2 * tg];
            #pragma unroll
            for (int nt = 0; nt < 8; nt++) {
                uint2 kk = *(const uint2*)&Kb[(nt * 8 + g) * 72 + ks * 8 + 2 * tg];
                mma16(sacc[nt], qlo.x, qhi.x, qlo.y, qhi.y, kk.x, kk.y);
            }
        }

        // mask (bit set = masked out); skip entirely when no bits set
        if (mb0 | mb1) {
            #pragma unroll
            for (int nt = 0; nt < 8; nt++) {
                int sh = nt * 8 + 2 * tg;
                if ((mb0 >> sh) & 1)       sacc[nt][0] = -1e30f;
                if ((mb0 >> (sh + 1)) & 1) sacc[nt][1] = -1e30f;
                if ((mb1 >> sh) & 1)       sacc[nt][2] = -1e30f;
                if ((mb1 >> (sh + 1)) & 1) sacc[nt][3] = -1e30f;
            }
        }

        float mx0 = -1e30f, mx1 = -1e30f;
        #pragma unroll
        for (int nt = 0; nt < 8; nt++) {
            mx0 = fmaxf(mx0, fmaxf(sacc[nt][0], sacc[nt][1]));
            mx1 = fmaxf(mx1, fmaxf(sacc[nt][2], sacc[nt][3]));
        }
        mx0 = fmaxf(mx0, __shfl_xor_sync(0xffffffffu, mx0, 1));
        mx0 = fmaxf(mx0, __shfl_xor_sync(0xffffffffu, mx0, 2));
        mx1 = fmaxf(mx1, __shfl_xor_sync(0xffffffffu, mx1, 1));
        mx1 = fmaxf(mx1, __shfl_xor_sync(0xffffffffu, mx1, 2));
        float mn0 = fmaxf(m0r, mx0), mn1 = fmaxf(m1r, mx1);
        float al0 = __expf(m0r - mn0), al1 = __expf(m1r - mn1);
        m0r = mn0; m1r = mn1;

        float p[8][4];
        float rs0 = 0.0f, rs1 = 0.0f;
        #pragma unroll
        for (int nt = 0; nt < 8; nt++) {
            p[nt][0] = __expf(sacc[nt][0] - mn0);
            p[nt][1] = __expf(sacc[nt][1] - mn0);
            p[nt][2] = __expf(sacc[nt][2] - mn1);
            p[nt][3] = __expf(sacc[nt][3] - mn1);
            rs0 += p[nt][0] + p[nt][1]; rs1 += p[nt][2] + p[nt][3];
        }
        // per-lane partial accumulation (al is quad-uniform; reduce at end)
        l0 = l0 * al0 + rs0;
        l1 = l1 * al1 + rs1;

        #pragma unroll
        for (int nt = 0; nt < 16; nt++) {
            oacc[nt][0] *= al0; oacc[nt][1] *= al0;
            oacc[nt][2] *= al1; oacc[nt][3] *= al1;
        }

        #pragma unroll
        for (int w = 0; w < 4; w++) {
            unsigned a0 = ph2(p[2*w][0],   p[2*w][1]);
            unsigned a1 = ph2(p[2*w][2],   p[2*w][3]);
            unsigned a2 = ph2(p[2*w+1][0], p[2*w+1][1]);
            unsigned a3 = ph2(p[2*w+1][2], p[2*w+1][3]);
            #pragma unroll
            for (int nt = 0; nt < 16; nt++) {
                uint2 vv = *(const uint2*)&Vb[(nt * 8 + g) * 40 + w * 8 + 2 * tg];
                mma16(oacc[nt], a0, a1, a2, a3, vv.x, vv.y);
            }
        }
        __syncthreads();
    }

    // epilogue: quad-reduce the deferred row sums, then normalize + store
    l0 += __shfl_xor_sync(0xffffffffu, l0, 1);
    l0 += __shfl_xor_sync(0xffffffffu, l0, 2);
    l1 += __shfl_xor_sync(0xffffffffu, l1, 1);
    l1 += __shfl_xor_sync(0xffffffffu, l1, 2);
    float il0 = 1.0f / l0, il1 = 1.0f / l1;
    int tok0 = qt * 128 + qrow + g;
    #pragma unroll
    for (int nt = 0; nt < 16; nt++) {
        int d = nt * 8 + 2 * tg;
        unsigned w0 = ph2(oacc[nt][0] * il0, oacc[nt][1] * il0);
        unsigned w1 = ph2(oacc[nt][2] * il1, oacc[nt][3] * il1);
        *(unsigned*)&ctxh[(((size_t)b * Tt + tok0) * Hh + h) * HD + d] = w0;
        *(unsigned*)&ctxh[(((size_t)b * Tt + tok0 + 8) * Hh + h) * HD + d] = w1;
    }
}

// ---------------------------------------------------------------------------
extern "C" void kernel_launch(void* const* d_in, const int* in_sizes, int n_in,
                              void* d_out, int out_size)
{
    const float*   x       = (const float*)d_in[0];
    const uint8_t* mask    = (const uint8_t*)d_in[1];
    const float*   cosT    = (const float*)d_in[2];
    const float*   sinT    = (const float*)d_in[3];
    const int*     pos     = (const int*)d_in[4];
    const float*   cache_k = (const float*)d_in[5];
    const float*   cache_v = (const float*)d_in[6];
    const float*   q_w     = (const float*)d_in[7];
    const float*   k_w     = (const float*)d_in[8];
    const float*   v_w     = (const float*)d_in[9];
    const float*   o_w     = (const float*)d_in[10];
    const float*   qn_w    = (const float*)d_in[11];
    const float*   kn_w    = (const float*)d_in[12];

    float* out_ctx = (float*)d_out;
    float* out_k   = out_ctx + (size_t)Bb * Tt * Hh * HD;
    float* out_v   = out_k   + (size_t)Bb * Gg * SS * HD;

    __half *xh, *wqkvh, *owh, *qhp, *ctxh, *khp, *vhp;
    float *qkv;
    unsigned long long *mbp;
    cudaGetSymbolAddress((void**)&xh,    g_xh);
    cudaGetSymbolAddress((void**)&wqkvh, g_wqkvh);
    cudaGetSymbolAddress((void**)&owh,   g_owh);
    cudaGetSymbolAddress((void**)&qkv,   g_qkv);
    cudaGetSymbolAddress((void**)&qhp,   g_qh);
    cudaGetSymbolAddress((void**)&ctxh,  g_ctxh);
    cudaGetSymbolAddress((void**)&khp,   g_kh);
    cudaGetSymbolAddress((void**)&vhp,   g_vh);
    cudaGetSymbolAddress((void**)&mbp,   g_mb);

    // Fork side stream: weight pack FIRST (main waits on it before the GEMM),
    // then copy/convert work + V-cache transpose (all input-only deps).
    cudaEventRecord(g_res.e0, 0);
    cudaStreamWaitEvent(g_res.s2, g_res.e0, 0);
    pack_wqkvT_kernel<<<dim3(32, 48), 256, 0, g_res.s2>>>(q_w, k_w, v_w, wqkvh);
    cudaEventRecord(g_res.e1, g_res.s2);
    {
        int n4 = Bb * Gg * CACHEN * HD / 4;
        int blocks = (n4 + 255) / 256;
        copy_cache_kernel<<<blocks, 256, 0, g_res.s2>>>(
            (const float4*)cache_k, (float4*)out_k, (uint2*)khp);
        copy_cache_kernel<<<blocks, 256, 0, g_res.s2>>>(
            (const float4*)cache_v, (float4*)out_v, nullptr);
        transpose_ow_kernel<<<dim3(64, 64), 256, 0, g_res.s2>>>(o_w, owh);
        int nm = Bb * Tt * 64;
        pack_mask_kernel<<<(nm + 255) / 256, 256, 0, g_res.s2>>>(mask, mbp);
        transpose_v_cache_kernel<<<dim3(CACHEN / 32, HD / 32, Bb * Gg), 256, 0, g_res.s2>>>(
            cache_v, vhp);
    }
    cudaEventRecord(g_res.e2, g_res.s2);

    // Main stream: x conversion (concurrent with the weight pack on s2).
    {
        int n4x = 2048 * 2048 / 4;
        conv_x_kernel<<<(n4x + 255) / 256, 256>>>((const float4*)x, (uint2*)xh, n4x);
    }
    cudaStreamWaitEvent(0, g_res.e1, 0);

    // fused QKV projection: [2048,2048] @ [3072,2048]^T, fp16 mma
    size_t gsmem = (size_t)(4 * 128 * 40) * 4;
    cudaFuncSetAttribute(gemm_h, cudaFuncAttributeMaxDynamicSharedMemorySize, (int)gsmem);
    gemm_h<<<dim3(24, 16), 256, gsmem>>>(xh, wqkvh, qkv, 2048, 3072, 2048);

    // new-token V: transpose+permute to scratch, and exact fp32 into v_full
    transpose_v_new_kernel<<<dim3(Tt / 32, HD / 32, Bb * Gg), 256>>>(qkv, vhp, out_v);

    // Fused RMSNorm + RoPE for Q and K in one launch
    const float scale = 0.08838834764831845f;   // 1/sqrt(128)
    norm_rope_qk_kernel<<<Bb * Tt * (Hh + Gg), 128>>>(
        qkv, qn_w, kn_w, cosT, sinT, pos, qhp, out_k, khp, scale);

    // Join: attention needs khp/vhp cache halves + mask bits; O-GEMM needs owh.
    cudaStreamWaitEvent(0, g_res.e2, 0);

    // attention (fp16 mma, 8 warps, 2 CTAs/SM, bitmask mask path)
    size_t smem = (size_t)(128 * 72 + 2 * 64 * 72 + 2 * 128 * 40) * 4;  // 114688
    cudaFuncSetAttribute(attn_h, cudaFuncAttributeMaxDynamicSharedMemorySize, (int)smem);
    attn_h<<<dim3(Tt / 128, Hh, Bb), 256, smem>>>(qhp, khp, vhp, mbp, ctxh);

    // output projection: [2048,2048] @ [2048,2048]^T, fp16 mma
    gemm_h<<<dim3(16, 16), 256, gsmem>>>(ctxh, owh, out_ctx, 2048, 2048, 2048);
}